// round 11
// baseline (speedup 1.0000x reference)
#include <cuda_runtime.h>
#include <cstdint>

#define B_TOTAL 8192
#define LEAK    0.01f
#define BN_EPS  1e-5f

__device__ float g_conv[64 * 90 * B_TOTAL];
__device__ float g_y1[16 * 50 * B_TOTAL];
__device__ float g_y2[8 * 66 * B_TOTAL];
__device__ float g_y3[8 * 48 * B_TOTAL];
__device__ float g_part1[800 * 32];
__device__ float g_part2[528 * 16];
__device__ float g_part3[384 * 16];
__device__ float g_bnA1[16], g_bnB1[16];
__device__ float g_bnA2[8],  g_bnB2[8];
__device__ float g_bnA3[8],  g_bnB3[8];

typedef unsigned long long u64;

__device__ __forceinline__ float lrelu(float v) { return v < 0.f ? LEAK * v : v; }
__device__ __forceinline__ float wsum(float v) {
#pragma unroll
    for (int s = 16; s; s >>= 1) v += __shfl_xor_sync(0xffffffffu, v, s);
    return v;
}
__device__ __forceinline__ u64 dup2f(float v) {
    u64 r; asm("mov.b64 %0, {%1, %1};" : "=l"(r) : "f"(v)); return r;
}
#define FMA2(d, a, b)   asm("fma.rn.f32x2 %0, %1, %2, %0;" : "+l"(d) : "l"(a), "l"(b))
#define UNPK(lo, hi, v) asm("mov.b64 {%0, %1}, %2;" : "=f"(lo), "=f"(hi) : "l"(v))
#define CH8(ar, s)                                              \
    FMA2(ar[0], s, wA.x); FMA2(ar[1], s, wA.y);                 \
    FMA2(ar[2], s, wB.x); FMA2(ar[3], s, wB.y);                 \
    FMA2(ar[4], s, wC.x); FMA2(ar[5], s, wC.y);                 \
    FMA2(ar[6], s, wD.x); FMA2(ar[7], s, wD.y);

// pack two f32 into bf16x2: low half = lo element, high half = hi element
#define PACKBF(d, hi, lo) asm("cvt.rn.bf16x2.f32 %0, %1, %2;" : "=r"(d) : "f"(hi), "f"(lo))

__device__ __forceinline__ void mma_bf16(float* d, const uint32_t* a, const uint32_t* b) {
    asm volatile(
        "mma.sync.aligned.m16n8k16.row.col.f32.bf16.bf16.f32 "
        "{%0,%1,%2,%3}, {%4,%5,%6,%7}, {%8,%9}, {%0,%1,%2,%3};"
        : "+f"(d[0]), "+f"(d[1]), "+f"(d[2]), "+f"(d[3])
        : "r"(a[0]), "r"(a[1]), "r"(a[2]), "r"(a[3]), "r"(b[0]), "r"(b[1]));
}

// ============================ K0: conv1 + lrelu ===============================
#define SMEM0 ((256 * 91 + 32 + 8) * 4)
__global__ void k0_conv1(const float* __restrict__ img,
                         const float* __restrict__ w1,
                         const float* __restrict__ b1) {
    extern __shared__ float sm0[];
    float* simg = sm0;
    float* sw   = sm0 + 256 * 91;
    float* sb   = sw + 32;
    const int t  = threadIdx.x;
    const int B0 = blockIdx.x * 256;
    const int c0 = blockIdx.y * 8;
#pragma unroll 1
    for (int i = 0; i < 90; ++i) {
        int f = i * 256 + t;
        int s = f / 90, off = f - s * 90;
        simg[s * 91 + off] = img[(B0 + s) * 90 + off];
    }
    if (t < 32) sw[t] = w1[c0 * 4 + t];
    if (t < 8)  sb[t] = b1[c0 + t];
    __syncthreads();
    const int q = t & 63, cg = t >> 6;
    float W00[2], W01[2], W10[2], W11[2], BB[2];
#pragma unroll
    for (int c2 = 0; c2 < 2; ++c2) {
        int cc = cg * 2 + c2;
        W00[c2] = sw[cc * 4 + 0]; W01[c2] = sw[cc * 4 + 1];
        W10[c2] = sw[cc * 4 + 2]; W11[c2] = sw[cc * 4 + 3];
        BB[c2]  = sb[cc];
    }
#pragma unroll 1
    for (int h = 0; h < 10; ++h) {
        float a[4][9], b[4][9];
        const bool hb = (h < 9);
#pragma unroll
        for (int s = 0; s < 4; ++s) {
            const float* rp = simg + (q * 4 + s) * 91 + h * 9;
#pragma unroll
            for (int w = 0; w < 9; ++w) { a[s][w] = rp[w]; b[s][w] = hb ? rp[9 + w] : 0.f; }
        }
#pragma unroll
        for (int c2 = 0; c2 < 2; ++c2) {
            const int c = c0 + cg * 2 + c2;
            float* op = g_conv + ((size_t)c * 90 + h * 9) * B_TOTAL + B0 + q * 4;
            const float w00 = W00[c2], w01 = W01[c2], w10 = W10[c2], w11 = W11[c2], bv = BB[c2];
#pragma unroll
            for (int w = 0; w < 9; ++w) {
                float v[4];
#pragma unroll
                for (int s = 0; s < 4; ++s) {
                    float t0 = fmaf(a[s][w], w00, bv);
                    if (w < 8) t0 = fmaf(a[s][w + 1], w01, t0);
                    t0 = fmaf(b[s][w], w10, t0);
                    if (w < 8) t0 = fmaf(b[s][w + 1], w11, t0);
                    v[s] = lrelu(t0);
                }
                ((float4*)(op + (size_t)w * B_TOTAL))[0] = make_float4(v[0], v[1], v[2], v[3]);
            }
        }
    }
}

// ============================ K1: LC1 via mma.sync bf16 (hi/lo) ===============
// grid (50, 16), block 256 (8 warps), 512 samples/block. K=576 in 36 k16 chunks.
// As: f32 [16][516]; Wp: bf16x2 hi/lo pairs [288][16][2].
#define AS_F   (16 * 516)
#define K1SM   (AS_F * 4 + 288 * 16 * 2 * 4 + 576 * 4 + 32 * 4)
__global__ void __launch_bounds__(256) k1_mma(const float* __restrict__ lcw,
                                              const float* __restrict__ lcb) {
    extern __shared__ __align__(16) char sm1[];
    float*    As   = (float*)sm1;                       // [16][516]
    uint32_t* Wp   = (uint32_t*)(sm1 + AS_F * 4);       // [288][16][2]
    int*      soff = (int*)(sm1 + AS_F * 4 + 36864);    // [576]
    float*    red  = (float*)(soff + 576);              // [32]
    const int t = threadIdx.x, lane = t & 31, wid = t >> 5;
    const int g = lane >> 2, tig = lane & 3;
    const int loc = blockIdx.x, B0 = blockIdx.y * 512;
    const int h = loc / 5, w = loc - h * 5;

    for (int k = t; k < 576; k += 256) {
        int c9 = k / 9, m9 = k - 9 * c9, i3 = m9 / 3, j3 = m9 - 3 * i3;
        int r = h + i3, cc = 2 * w + j3;
        soff[k] = (r >= 1 && r <= 10 && cc >= 1 && cc <= 9)
                  ? ((c9 * 10 + r - 1) * 9 + (cc - 1)) * B_TOTAL : -1;
    }
    if (t < 32) red[t] = 0.f;
    // W pack: pairs (k2 = k/2) -> bf16x2 hi & lo
    for (int f = t; f < 288 * 16; f += 256) {
        int k2 = f >> 4, n = f & 15;
        int ka = 2 * k2, kb = 2 * k2 + 1;
        float w0 = lcw[((size_t)(n * 64 + ka / 9) * 50 + loc) * 9 + ka % 9];
        float w1 = lcw[((size_t)(n * 64 + kb / 9) * 50 + loc) * 9 + kb % 9];
        uint32_t hi; PACKBF(hi, w1, w0);
        float r0 = w0 - __uint_as_float(hi << 16);
        float r1 = w1 - __uint_as_float(hi & 0xffff0000u);
        uint32_t lo; PACKBF(lo, r1, r0);
        Wp[f * 2] = hi; Wp[f * 2 + 1] = lo;
    }
    __syncthreads();

    float D[4][2][4] = {};

#pragma unroll 1
    for (int c = 0; c < 36; ++c) {
        if (c) __syncthreads();
        // stage A chunk: 2048 float4, 8 per thread
#pragma unroll
        for (int i = 0; i < 8; ++i) {
            int f = i * 256 + t;
            int row = f >> 7, c4 = f & 127;
            int off = soff[c * 16 + row];
            float4 v = make_float4(0.f, 0.f, 0.f, 0.f);
            if (off >= 0) v = *(const float4*)(g_conv + off + B0 + c4 * 4);
            ((float4*)(As + row * 516))[c4] = v;
        }
        __syncthreads();

        // B frags for this chunk
        uint32_t bh[2][2], bl[2][2];
#pragma unroll
        for (int nt = 0; nt < 2; ++nt) {
            int n = nt * 8 + g;
            int i0 = ((c * 8 + tig) * 16 + n) * 2;
            int i1 = ((c * 8 + tig + 4) * 16 + n) * 2;
            bh[nt][0] = Wp[i0]; bl[nt][0] = Wp[i0 + 1];
            bh[nt][1] = Wp[i1]; bl[nt][1] = Wp[i1 + 1];
        }
#pragma unroll
        for (int mt = 0; mt < 4; ++mt) {
            const int sg = wid * 64 + mt * 16 + g;
            float x00 = As[(2 * tig) * 516 + sg],     x01 = As[(2 * tig + 1) * 516 + sg];
            float x10 = As[(2 * tig) * 516 + sg + 8], x11 = As[(2 * tig + 1) * 516 + sg + 8];
            float x20 = As[(2 * tig + 8) * 516 + sg],     x21 = As[(2 * tig + 9) * 516 + sg];
            float x30 = As[(2 * tig + 8) * 516 + sg + 8], x31 = As[(2 * tig + 9) * 516 + sg + 8];
            uint32_t ah[4], al[4];
            PACKBF(ah[0], x01, x00);
            PACKBF(ah[1], x11, x10);
            PACKBF(ah[2], x21, x20);
            PACKBF(ah[3], x31, x30);
            float r0, r1;
            r0 = x00 - __uint_as_float(ah[0] << 16); r1 = x01 - __uint_as_float(ah[0] & 0xffff0000u);
            PACKBF(al[0], r1, r0);
            r0 = x10 - __uint_as_float(ah[1] << 16); r1 = x11 - __uint_as_float(ah[1] & 0xffff0000u);
            PACKBF(al[1], r1, r0);
            r0 = x20 - __uint_as_float(ah[2] << 16); r1 = x21 - __uint_as_float(ah[2] & 0xffff0000u);
            PACKBF(al[2], r1, r0);
            r0 = x30 - __uint_as_float(ah[3] << 16); r1 = x31 - __uint_as_float(ah[3] & 0xffff0000u);
            PACKBF(al[3], r1, r0);
#pragma unroll
            for (int nt = 0; nt < 2; ++nt) {
                mma_bf16(D[mt][nt], ah, bh[nt]);
                mma_bf16(D[mt][nt], ah, bl[nt]);
                mma_bf16(D[mt][nt], al, bh[nt]);
            }
        }
    }

    // epilogue: bias + lrelu + store + stats
    float bv[2][2];
#pragma unroll
    for (int nt = 0; nt < 2; ++nt)
#pragma unroll
        for (int e = 0; e < 2; ++e)
            bv[nt][e] = lcb[(nt * 8 + 2 * tig + e) * 50 + loc];
    float scol[4] = {0.f, 0.f, 0.f, 0.f}, qcol[4] = {0.f, 0.f, 0.f, 0.f};
#pragma unroll
    for (int mt = 0; mt < 4; ++mt) {
#pragma unroll
        for (int nt = 0; nt < 2; ++nt) {
#pragma unroll
            for (int e = 0; e < 2; ++e) {
                const int o = nt * 8 + 2 * tig + e;
                float* base = g_y1 + ((size_t)o * 50 + loc) * B_TOTAL + B0 + wid * 64 + mt * 16;
                float v0 = lrelu(D[mt][nt][e]     + bv[nt][e]);   // row g
                float v1 = lrelu(D[mt][nt][e + 2] + bv[nt][e]);   // row g+8
                base[g] = v0;
                base[g + 8] = v1;
                scol[nt * 2 + e] += v0 + v1;
                qcol[nt * 2 + e] += v0 * v0 + v1 * v1;
            }
        }
    }
#pragma unroll
    for (int idx = 0; idx < 4; ++idx) {
        float s = scol[idx], qq = qcol[idx];
#pragma unroll
        for (int m = 4; m < 32; m <<= 1) {
            s  += __shfl_xor_sync(0xffffffffu, s, m);
            qq += __shfl_xor_sync(0xffffffffu, qq, m);
        }
        if (g == 0) {
            int o = (idx >> 1) * 8 + 2 * tig + (idx & 1);
            atomicAdd(&red[2 * o], s);
            atomicAdd(&red[2 * o + 1], qq);
        }
    }
    __syncthreads();
    if (t < 32) g_part1[(blockIdx.y * 50 + loc) * 32 + t] = red[t];
}

// ============================ K3: BN1(folded) + pad + LC2 (R4) ================
__global__ void __launch_bounds__(128, 4) k3_lc2(const float* __restrict__ lcw,
                                                 const float* __restrict__ lcb) {
    __shared__ __align__(16) u64 Wd[512];
    __shared__ float biasc[8];
    __shared__ int soff[68];
    __shared__ float red[16];
    const int t = threadIdx.x, loc = blockIdx.x, B0 = blockIdx.y * 1024;
    const int h2 = loc / 6, w2 = loc - h2 * 6;
#pragma unroll
    for (int rr = 0; rr < 4; ++rr) {
        int idx = rr * 128 + t;
        int o = idx & 7, k = idx >> 3, c = k >> 2;
        float wv = lcw[(size_t)((o * 16 + c) * 66 + loc) * 4 + (k & 3)];
        Wd[idx] = dup2f(wv * g_bnA1[c]);
    }
    for (int k = t; k < 68; k += 128) {
        int v = -1;
        if (k < 64) {
            int c = k >> 2, mm = k & 3;
            int hp = h2 + (mm >> 1), wp = w2 + (mm & 1);
            if (hp >= 1 && hp <= 10 && wp >= 1 && wp <= 5)
                v = (c * 50 + (hp - 1) * 5 + (wp - 1)) * B_TOTAL;
        }
        soff[k] = v;
    }
    if (t < 16) red[t] = 0.f;
    if (t < 8) {
        float s = 0.f;
#pragma unroll 1
        for (int k = 0; k < 64; ++k) {
            int c = k >> 2, mm = k & 3;
            int hp = h2 + (mm >> 1), wp = w2 + (mm & 1);
            if (hp >= 1 && hp <= 10 && wp >= 1 && wp <= 5)
                s += lcw[(size_t)((t * 16 + c) * 66 + loc) * 4 + mm] * g_bnB1[c];
        }
        biasc[t] = s;
    }
    __syncthreads();
    const float* gA = g_y1 + B0 + t * 8;
    u64 acc[4][8] = {};
    ulonglong2 f0a, f0b, f1a, f1b;
    f0a.x = f0a.y = 0ULL; f0b = f0a; f1a = f0a; f1b = f0a;
    if (soff[0] >= 0) { const ulonglong2* p = (const ulonglong2*)(gA + soff[0]); f0a = p[0]; f0b = p[1]; }
    if (soff[1] >= 0) { const ulonglong2* p = (const ulonglong2*)(gA + soff[1]); f1a = p[0]; f1b = p[1]; }
#define LCB3(FA, FB, KIDX) do {                                              \
    ulonglong2 a01 = FA, a23 = FB;                                           \
    { int _o = soff[(KIDX) + 2];                                             \
      FA.x = 0ULL; FA.y = 0ULL; FB = FA;                                     \
      if (_o >= 0) { const ulonglong2* _p = (const ulonglong2*)(gA + _o);    \
          FA = _p[0]; FB = _p[1]; } }                                        \
    const ulonglong2* wp = (const ulonglong2*)(Wd + (size_t)(KIDX) * 8);     \
    ulonglong2 wA = wp[0], wB = wp[1], wC = wp[2], wD = wp[3];               \
    CH8(acc[0], a01.x); CH8(acc[1], a01.y);                                  \
    CH8(acc[2], a23.x); CH8(acc[3], a23.y);                                  \
} while (0)
#pragma unroll 2
    for (int k = 0; k < 64; k += 2) { LCB3(f0a, f0b, k); LCB3(f1a, f1b, k + 1); }
#pragma unroll
    for (int o = 0; o < 8; ++o) {
        const float bvv = lcb[o * 66 + loc] + biasc[o];
        float v[8];
#pragma unroll
        for (int p = 0; p < 4; ++p) UNPK(v[2 * p], v[2 * p + 1], acc[p][o]);
#pragma unroll
        for (int p = 0; p < 8; ++p) v[p] = lrelu(v[p] + bvv);
        float* dst = g_y2 + ((size_t)o * 66 + loc) * B_TOTAL + B0 + t * 8;
        ((float4*)dst)[0] = make_float4(v[0], v[1], v[2], v[3]);
        ((float4*)dst)[1] = make_float4(v[4], v[5], v[6], v[7]);
        float s = wsum(v[0]+v[1]+v[2]+v[3]+v[4]+v[5]+v[6]+v[7]);
        float q = wsum(v[0]*v[0]+v[1]*v[1]+v[2]*v[2]+v[3]*v[3]
                     + v[4]*v[4]+v[5]*v[5]+v[6]*v[6]+v[7]*v[7]);
        if ((t & 31) == 0) { atomicAdd(&red[o * 2], s); atomicAdd(&red[o * 2 + 1], q); }
    }
    __syncthreads();
    if (t < 16) g_part2[(blockIdx.y * 66 + loc) * 16 + t] = red[t];
}

// ============================ K5: BN2(folded) + pad + LC3 (R4) ================
__global__ void __launch_bounds__(128, 4) k5_lc3(const float* __restrict__ lcw,
                                                 const float* __restrict__ lcb) {
    __shared__ __align__(16) u64 Wd[256];
    __shared__ float biasc[8];
    __shared__ int soff[36];
    __shared__ float red[16];
    const int t = threadIdx.x, loc = blockIdx.x, B0 = blockIdx.y * 1024;
    const int h3 = loc >> 2, w3 = loc & 3;
#pragma unroll
    for (int rr = 0; rr < 2; ++rr) {
        int idx = rr * 128 + t;
        int o = idx & 7, k = idx >> 3, c = k >> 2;
        float wv = lcw[(size_t)((o * 8 + c) * 48 + loc) * 4 + (k & 3)];
        Wd[idx] = dup2f(wv * g_bnA2[c]);
    }
    for (int k = t; k < 36; k += 128) {
        int v = -1;
        if (k < 32) {
            int c = k >> 2, mm = k & 3;
            int hp = h3 + (mm >> 1), wp = 2 * w3 + (mm & 1);
            if (hp >= 1 && hp <= 11 && wp >= 1 && wp <= 6)
                v = (c * 66 + (hp - 1) * 6 + (wp - 1)) * B_TOTAL;
        }
        soff[k] = v;
    }
    if (t < 16) red[t] = 0.f;
    if (t < 8) {
        float s = 0.f;
#pragma unroll 1
        for (int k = 0; k < 32; ++k) {
            int c = k >> 2, mm = k & 3;
            int hp = h3 + (mm >> 1), wp = 2 * w3 + (mm & 1);
            if (hp >= 1 && hp <= 11 && wp >= 1 && wp <= 6)
                s += lcw[(size_t)((t * 8 + c) * 48 + loc) * 4 + mm] * g_bnB2[c];
        }
        biasc[t] = s;
    }
    __syncthreads();
    const float* gA = g_y2 + B0 + t * 8;
    u64 acc[4][8] = {};
    ulonglong2 f0a, f0b, f1a, f1b;
    f0a.x = f0a.y = 0ULL; f0b = f0a; f1a = f0a; f1b = f0a;
    if (soff[0] >= 0) { const ulonglong2* p = (const ulonglong2*)(gA + soff[0]); f0a = p[0]; f0b = p[1]; }
    if (soff[1] >= 0) { const ulonglong2* p = (const ulonglong2*)(gA + soff[1]); f1a = p[0]; f1b = p[1]; }
#pragma unroll 2
    for (int k = 0; k < 32; k += 2) { LCB3(f0a, f0b, k); LCB3(f1a, f1b, k + 1); }
#pragma unroll
    for (int o = 0; o < 8; ++o) {
        const float bvv = lcb[o * 48 + loc] + biasc[o];
        float v[8];
#pragma unroll
        for (int p = 0; p < 4; ++p) UNPK(v[2 * p], v[2 * p + 1], acc[p][o]);
#pragma unroll
        for (int p = 0; p < 8; ++p) v[p] = lrelu(v[p] + bvv);
        float* dst = g_y3 + ((size_t)o * 48 + loc) * B_TOTAL + B0 + t * 8;
        ((float4*)dst)[0] = make_float4(v[0], v[1], v[2], v[3]);
        ((float4*)dst)[1] = make_float4(v[4], v[5], v[6], v[7]);
        float s = wsum(v[0]+v[1]+v[2]+v[3]+v[4]+v[5]+v[6]+v[7]);
        float q = wsum(v[0]*v[0]+v[1]*v[1]+v[2]*v[2]+v[3]*v[3]
                     + v[4]*v[4]+v[5]*v[5]+v[6]*v[6]+v[7]*v[7]);
        if ((t & 31) == 0) { atomicAdd(&red[o * 2], s); atomicAdd(&red[o * 2 + 1], q); }
    }
    __syncthreads();
    if (t < 16) g_part3[(blockIdx.y * 48 + loc) * 16 + t] = red[t];
}

// ============================ stat reducer ====================================
__global__ void kred(int stage, int nb, int nch, float invN,
                     const float* __restrict__ gamma, const float* __restrict__ beta) {
    __shared__ float sm[1024];
    const float* part = (stage == 0) ? g_part1 : (stage == 1) ? g_part2 : g_part3;
    float* bnA = (stage == 0) ? g_bnA1 : (stage == 1) ? g_bnA2 : g_bnA3;
    float* bnB = (stage == 0) ? g_bnB1 : (stage == 1) ? g_bnB2 : g_bnB3;
    const int t = threadIdx.x;
    const int slots = 2 * nch;
    const int grp = t % slots, lane = t / slots, per = blockDim.x / slots;
    float s = 0.f;
    for (int i = lane; i < nb; i += per) s += part[i * slots + grp];
    sm[t] = s;
    __syncthreads();
    for (int step = per >> 1; step > 0; step >>= 1) {
        if (lane < step) sm[t] += sm[t + step * slots];
        __syncthreads();
    }
    if (t < nch) {
        float sum = sm[t * 2], sq = sm[t * 2 + 1];
        float mean = sum * invN;
        float var = sq * invN - mean * mean;
        float rs = rsqrtf(var + BN_EPS);
        float gg = gamma[t];
        bnA[t] = gg * rs;
        bnB[t] = beta[t] - mean * gg * rs;
    }
}

// ============================ K7: BN3 + transpose to output ===================
__global__ void k7_out(float* __restrict__ out) {
    __shared__ float tile[32][65];
    __shared__ float a3[8], b3[8];
    const int t = threadIdx.x;
    const int f0 = blockIdx.x * 32, b0 = blockIdx.y * 64;
    if (t < 8) { a3[t] = g_bnA3[t]; b3[t] = g_bnB3[t]; }
    __syncthreads();
#pragma unroll
    for (int r = 0; r < 8; ++r) {
        int f = r * 4 + (t >> 6), b = t & 63;
        float v = g_y3[(size_t)(f0 + f) * B_TOTAL + b0 + b];
        int c = (f0 + f) / 48;
        tile[f][b] = fmaf(a3[c], v, b3[c]);
    }
    __syncthreads();
#pragma unroll
    for (int r = 0; r < 8; ++r) {
        int f = t & 31, b = r * 8 + (t >> 5);
        out[(size_t)(b0 + b) * 384 + f0 + f] = tile[f][b];
    }
}

// ============================ launch ==========================================
extern "C" void kernel_launch(void* const* d_in, const int* in_sizes, int n_in,
                              void* d_out, int out_size) {
    const float* image = (const float*)d_in[0];
    const float* c1w   = (const float*)d_in[1];
    const float* c1b   = (const float*)d_in[2];
    const float* lc1w  = (const float*)d_in[3];
    const float* lc1b  = (const float*)d_in[4];
    const float* lc2w  = (const float*)d_in[5];
    const float* lc2b  = (const float*)d_in[6];
    const float* lc3w  = (const float*)d_in[7];
    const float* lc3b  = (const float*)d_in[8];
    const float* g1    = (const float*)d_in[9];
    const float* be1   = (const float*)d_in[10];
    const float* g2    = (const float*)d_in[11];
    const float* be2   = (const float*)d_in[12];
    const float* g3    = (const float*)d_in[13];
    const float* be3   = (const float*)d_in[14];
    float* out = (float*)d_out;

    cudaFuncSetAttribute(k0_conv1, cudaFuncAttributeMaxDynamicSharedMemorySize, SMEM0);
    cudaFuncSetAttribute(k1_mma,   cudaFuncAttributeMaxDynamicSharedMemorySize, K1SM);

    k0_conv1<<<dim3(32, 8),  256, SMEM0>>>(image, c1w, c1b);
    k1_mma  <<<dim3(50, 16), 256, K1SM>>>(lc1w, lc1b);
    kred    <<<1, 1024>>>(0, 800, 16, 1.0f / (8192.0f * 50.0f), g1, be1);
    k3_lc2  <<<dim3(66, 8),  128>>>(lc2w, lc2b);
    kred    <<<1, 1024>>>(1, 528, 8, 1.0f / (8192.0f * 66.0f), g2, be2);
    k5_lc3  <<<dim3(48, 8),  128>>>(lc3w, lc3b);
    kred    <<<1, 1024>>>(2, 384, 8, 1.0f / (8192.0f * 48.0f), g3, be3);
    k7_out  <<<dim3(12, 128), 256>>>(out);
}

// round 12
// speedup vs baseline: 1.1367x; 1.1367x over previous
#include <cuda_runtime.h>
#include <cstdint>

#define B_TOTAL 8192
#define LEAK    0.01f
#define BN_EPS  1e-5f

__device__ float g_conv[64 * 90 * B_TOTAL];
__device__ float g_y1[16 * 50 * B_TOTAL];
__device__ float g_y2[8 * 66 * B_TOTAL];
__device__ float g_y3[8 * 48 * B_TOTAL];
__device__ float g_part1[800 * 32];
__device__ float g_part2[528 * 16];
__device__ float g_part3[384 * 16];
__device__ float g_bnA1[16], g_bnB1[16];
__device__ float g_bnA2[8],  g_bnB2[8];
__device__ float g_bnA3[8],  g_bnB3[8];

typedef unsigned long long u64;

__device__ __forceinline__ float lrelu(float v) { return v < 0.f ? LEAK * v : v; }
__device__ __forceinline__ float wsum(float v) {
#pragma unroll
    for (int s = 16; s; s >>= 1) v += __shfl_xor_sync(0xffffffffu, v, s);
    return v;
}
__device__ __forceinline__ u64 dup2f(float v) {
    u64 r; asm("mov.b64 %0, {%1, %1};" : "=l"(r) : "f"(v)); return r;
}
#define FMA2(d, a, b)   asm("fma.rn.f32x2 %0, %1, %2, %0;" : "+l"(d) : "l"(a), "l"(b))
#define UNPK(lo, hi, v) asm("mov.b64 {%0, %1}, %2;" : "=f"(lo), "=f"(hi) : "l"(v))
#define CH8(ar, s)                                              \
    FMA2(ar[0], s, wA.x); FMA2(ar[1], s, wA.y);                 \
    FMA2(ar[2], s, wB.x); FMA2(ar[3], s, wB.y);                 \
    FMA2(ar[4], s, wC.x); FMA2(ar[5], s, wC.y);                 \
    FMA2(ar[6], s, wD.x); FMA2(ar[7], s, wD.y);

// pack two f32 into bf16x2: low 16 bits = lo arg, high 16 bits = hi arg
#define PACKBF(d, hi, lo) asm("cvt.rn.bf16x2.f32 %0, %1, %2;" : "=r"(d) : "f"(hi), "f"(lo))

__device__ __forceinline__ void mma_bf16(float* d, const uint32_t* a, const uint32_t* b) {
    asm volatile(
        "mma.sync.aligned.m16n8k16.row.col.f32.bf16.bf16.f32 "
        "{%0,%1,%2,%3}, {%4,%5,%6,%7}, {%8,%9}, {%0,%1,%2,%3};"
        : "+f"(d[0]), "+f"(d[1]), "+f"(d[2]), "+f"(d[3])
        : "r"(a[0]), "r"(a[1]), "r"(a[2]), "r"(a[3]), "r"(b[0]), "r"(b[1]));
}

// ============================ K0: conv1 + lrelu ===============================
#define SMEM0 ((256 * 91 + 32 + 8) * 4)
__global__ void k0_conv1(const float* __restrict__ img,
                         const float* __restrict__ w1,
                         const float* __restrict__ b1) {
    extern __shared__ float sm0[];
    float* simg = sm0;
    float* sw   = sm0 + 256 * 91;
    float* sb   = sw + 32;
    const int t  = threadIdx.x;
    const int B0 = blockIdx.x * 256;
    const int c0 = blockIdx.y * 8;
#pragma unroll 1
    for (int i = 0; i < 90; ++i) {
        int f = i * 256 + t;
        int s = f / 90, off = f - s * 90;
        simg[s * 91 + off] = img[(B0 + s) * 90 + off];
    }
    if (t < 32) sw[t] = w1[c0 * 4 + t];
    if (t < 8)  sb[t] = b1[c0 + t];
    __syncthreads();
    const int q = t & 63, cg = t >> 6;
    float W00[2], W01[2], W10[2], W11[2], BB[2];
#pragma unroll
    for (int c2 = 0; c2 < 2; ++c2) {
        int cc = cg * 2 + c2;
        W00[c2] = sw[cc * 4 + 0]; W01[c2] = sw[cc * 4 + 1];
        W10[c2] = sw[cc * 4 + 2]; W11[c2] = sw[cc * 4 + 3];
        BB[c2]  = sb[cc];
    }
#pragma unroll 1
    for (int h = 0; h < 10; ++h) {
        float a[4][9], b[4][9];
        const bool hb = (h < 9);
#pragma unroll
        for (int s = 0; s < 4; ++s) {
            const float* rp = simg + (q * 4 + s) * 91 + h * 9;
#pragma unroll
            for (int w = 0; w < 9; ++w) { a[s][w] = rp[w]; b[s][w] = hb ? rp[9 + w] : 0.f; }
        }
#pragma unroll
        for (int c2 = 0; c2 < 2; ++c2) {
            const int c = c0 + cg * 2 + c2;
            float* op = g_conv + ((size_t)c * 90 + h * 9) * B_TOTAL + B0 + q * 4;
            const float w00 = W00[c2], w01 = W01[c2], w10 = W10[c2], w11 = W11[c2], bv = BB[c2];
#pragma unroll
            for (int w = 0; w < 9; ++w) {
                float v[4];
#pragma unroll
                for (int s = 0; s < 4; ++s) {
                    float t0 = fmaf(a[s][w], w00, bv);
                    if (w < 8) t0 = fmaf(a[s][w + 1], w01, t0);
                    t0 = fmaf(b[s][w], w10, t0);
                    if (w < 8) t0 = fmaf(b[s][w + 1], w11, t0);
                    v[s] = lrelu(t0);
                }
                ((float4*)(op + (size_t)w * B_TOTAL))[0] = make_float4(v[0], v[1], v[2], v[3]);
            }
        }
    }
}

// ============================ K1: LC1 via mma.sync bf16 (hi/lo v2) ============
// grid (50, 16), block 256 (8 warps), 512 samples/block. K=576 in 36 k16 chunks.
// A staged PRE-PACKED as bf16x2 pairs: Ah/Al u32 [8 k2][520]. W: [288][16][2].
#define AROW   520
#define K1SM   (2 * 8 * AROW * 4 + 288 * 16 * 2 * 4 + 576 * 4 + 32 * 4)
__global__ void __launch_bounds__(256, 2) k1_mma(const float* __restrict__ lcw,
                                                 const float* __restrict__ lcb) {
    extern __shared__ __align__(16) char sm1[];
    uint32_t* Ah   = (uint32_t*)sm1;                         // [8][520]
    uint32_t* Al   = Ah + 8 * AROW;                          // [8][520]
    uint32_t* Wp   = Al + 8 * AROW;                          // [288][16][2]
    int*      soff = (int*)(Wp + 288 * 16 * 2);              // [576]
    float*    red  = (float*)(soff + 576);                   // [32]
    const int t = threadIdx.x, lane = t & 31, wid = t >> 5;
    const int g = lane >> 2, tig = lane & 3;
    const int loc = blockIdx.x, B0 = blockIdx.y * 512;
    const int h = loc / 5, w = loc - h * 5;

    for (int k = t; k < 576; k += 256) {
        int c9 = k / 9, m9 = k - 9 * c9, i3 = m9 / 3, j3 = m9 - 3 * i3;
        int r = h + i3, cc = 2 * w + j3;
        soff[k] = (r >= 1 && r <= 10 && cc >= 1 && cc <= 9)
                  ? ((c9 * 10 + r - 1) * 9 + (cc - 1)) * B_TOTAL : -1;
    }
    if (t < 32) red[t] = 0.f;
    // W pack: pairs (k2) -> bf16x2 hi & lo
    for (int f = t; f < 288 * 16; f += 256) {
        int k2 = f >> 4, n = f & 15;
        int ka = 2 * k2, kb = 2 * k2 + 1;
        float w0 = lcw[((size_t)(n * 64 + ka / 9) * 50 + loc) * 9 + ka % 9];
        float w1 = lcw[((size_t)(n * 64 + kb / 9) * 50 + loc) * 9 + kb % 9];
        uint32_t hi; PACKBF(hi, w1, w0);
        float r0 = w0 - __uint_as_float(hi << 16);
        float r1 = w1 - __uint_as_float(hi & 0xffff0000u);
        uint32_t lo; PACKBF(lo, r1, r0);
        Wp[f * 2] = hi; Wp[f * 2 + 1] = lo;
    }
    __syncthreads();

    float D[4][2][4] = {};

#pragma unroll 1
    for (int c = 0; c < 36; ++c) {
        if (c) __syncthreads();
        // stage A chunk packed: 8 k2-rows x 512 samples; thread does 4 quad-tasks
#pragma unroll
        for (int i = 0; i < 4; ++i) {
            int f = i * 256 + t;
            int k2 = f >> 7, q4 = f & 127;
            int o0 = soff[c * 16 + 2 * k2], o1 = soff[c * 16 + 2 * k2 + 1];
            float4 v0 = make_float4(0.f, 0.f, 0.f, 0.f), v1 = v0;
            if (o0 >= 0) v0 = *(const float4*)(g_conv + o0 + B0 + q4 * 4);
            if (o1 >= 0) v1 = *(const float4*)(g_conv + o1 + B0 + q4 * 4);
            uint32_t hx, hy, hz, hw, lx, ly, lz, lw;
            PACKBF(hx, v1.x, v0.x); PACKBF(hy, v1.y, v0.y);
            PACKBF(hz, v1.z, v0.z); PACKBF(hw, v1.w, v0.w);
            float ra, rb;
            ra = v0.x - __uint_as_float(hx << 16); rb = v1.x - __uint_as_float(hx & 0xffff0000u);
            PACKBF(lx, rb, ra);
            ra = v0.y - __uint_as_float(hy << 16); rb = v1.y - __uint_as_float(hy & 0xffff0000u);
            PACKBF(ly, rb, ra);
            ra = v0.z - __uint_as_float(hz << 16); rb = v1.z - __uint_as_float(hz & 0xffff0000u);
            PACKBF(lz, rb, ra);
            ra = v0.w - __uint_as_float(hw << 16); rb = v1.w - __uint_as_float(hw & 0xffff0000u);
            PACKBF(lw, rb, ra);
            ((uint4*)(Ah + k2 * AROW))[q4] = make_uint4(hx, hy, hz, hw);
            ((uint4*)(Al + k2 * AROW))[q4] = make_uint4(lx, ly, lz, lw);
        }
        __syncthreads();

        // B frags
        uint32_t bh[2][2], bl[2][2];
#pragma unroll
        for (int nt = 0; nt < 2; ++nt) {
            int n = nt * 8 + g;
            int i0 = ((c * 8 + tig) * 16 + n) * 2;
            int i1 = ((c * 8 + tig + 4) * 16 + n) * 2;
            bh[nt][0] = Wp[i0]; bl[nt][0] = Wp[i0 + 1];
            bh[nt][1] = Wp[i1]; bl[nt][1] = Wp[i1 + 1];
        }
#pragma unroll
        for (int mt = 0; mt < 4; ++mt) {
            const int sg = wid * 64 + mt * 16 + g;
            uint32_t ah[4], al[4];
            ah[0] = Ah[tig * AROW + sg];           al[0] = Al[tig * AROW + sg];
            ah[1] = Ah[tig * AROW + sg + 8];       al[1] = Al[tig * AROW + sg + 8];
            ah[2] = Ah[(tig + 4) * AROW + sg];     al[2] = Al[(tig + 4) * AROW + sg];
            ah[3] = Ah[(tig + 4) * AROW + sg + 8]; al[3] = Al[(tig + 4) * AROW + sg + 8];
#pragma unroll
            for (int nt = 0; nt < 2; ++nt) {
                mma_bf16(D[mt][nt], ah, bh[nt]);
                mma_bf16(D[mt][nt], ah, bl[nt]);
                mma_bf16(D[mt][nt], al, bh[nt]);
            }
        }
    }

    // epilogue: bias + lrelu + store + stats (validated in R11)
    float bv[2][2];
#pragma unroll
    for (int nt = 0; nt < 2; ++nt)
#pragma unroll
        for (int e = 0; e < 2; ++e)
            bv[nt][e] = lcb[(nt * 8 + 2 * tig + e) * 50 + loc];
    float scol[4] = {0.f, 0.f, 0.f, 0.f}, qcol[4] = {0.f, 0.f, 0.f, 0.f};
#pragma unroll
    for (int mt = 0; mt < 4; ++mt) {
#pragma unroll
        for (int nt = 0; nt < 2; ++nt) {
#pragma unroll
            for (int e = 0; e < 2; ++e) {
                const int o = nt * 8 + 2 * tig + e;
                float* base = g_y1 + ((size_t)o * 50 + loc) * B_TOTAL + B0 + wid * 64 + mt * 16;
                float v0 = lrelu(D[mt][nt][e]     + bv[nt][e]);
                float v1 = lrelu(D[mt][nt][e + 2] + bv[nt][e]);
                base[g] = v0;
                base[g + 8] = v1;
                scol[nt * 2 + e] += v0 + v1;
                qcol[nt * 2 + e] += v0 * v0 + v1 * v1;
            }
        }
    }
#pragma unroll
    for (int idx = 0; idx < 4; ++idx) {
        float s = scol[idx], qq = qcol[idx];
#pragma unroll
        for (int m = 4; m < 32; m <<= 1) {
            s  += __shfl_xor_sync(0xffffffffu, s, m);
            qq += __shfl_xor_sync(0xffffffffu, qq, m);
        }
        if (g == 0) {
            int o = (idx >> 1) * 8 + 2 * tig + (idx & 1);
            atomicAdd(&red[2 * o], s);
            atomicAdd(&red[2 * o + 1], qq);
        }
    }
    __syncthreads();
    if (t < 32) g_part1[(blockIdx.y * 50 + loc) * 32 + t] = red[t];
}

// ============================ K3: BN1(folded) + pad + LC2 (R4) ================
__global__ void __launch_bounds__(128, 4) k3_lc2(const float* __restrict__ lcw,
                                                 const float* __restrict__ lcb) {
    __shared__ __align__(16) u64 Wd[512];
    __shared__ float biasc[8];
    __shared__ int soff[68];
    __shared__ float red[16];
    const int t = threadIdx.x, loc = blockIdx.x, B0 = blockIdx.y * 1024;
    const int h2 = loc / 6, w2 = loc - h2 * 6;
#pragma unroll
    for (int rr = 0; rr < 4; ++rr) {
        int idx = rr * 128 + t;
        int o = idx & 7, k = idx >> 3, c = k >> 2;
        float wv = lcw[(size_t)((o * 16 + c) * 66 + loc) * 4 + (k & 3)];
        Wd[idx] = dup2f(wv * g_bnA1[c]);
    }
    for (int k = t; k < 68; k += 128) {
        int v = -1;
        if (k < 64) {
            int c = k >> 2, mm = k & 3;
            int hp = h2 + (mm >> 1), wp = w2 + (mm & 1);
            if (hp >= 1 && hp <= 10 && wp >= 1 && wp <= 5)
                v = (c * 50 + (hp - 1) * 5 + (wp - 1)) * B_TOTAL;
        }
        soff[k] = v;
    }
    if (t < 16) red[t] = 0.f;
    if (t < 8) {
        float s = 0.f;
#pragma unroll 1
        for (int k = 0; k < 64; ++k) {
            int c = k >> 2, mm = k & 3;
            int hp = h2 + (mm >> 1), wp = w2 + (mm & 1);
            if (hp >= 1 && hp <= 10 && wp >= 1 && wp <= 5)
                s += lcw[(size_t)((t * 16 + c) * 66 + loc) * 4 + mm] * g_bnB1[c];
        }
        biasc[t] = s;
    }
    __syncthreads();
    const float* gA = g_y1 + B0 + t * 8;
    u64 acc[4][8] = {};
    ulonglong2 f0a, f0b, f1a, f1b;
    f0a.x = f0a.y = 0ULL; f0b = f0a; f1a = f0a; f1b = f0a;
    if (soff[0] >= 0) { const ulonglong2* p = (const ulonglong2*)(gA + soff[0]); f0a = p[0]; f0b = p[1]; }
    if (soff[1] >= 0) { const ulonglong2* p = (const ulonglong2*)(gA + soff[1]); f1a = p[0]; f1b = p[1]; }
#define LCB3(FA, FB, KIDX) do {                                              \
    ulonglong2 a01 = FA, a23 = FB;                                           \
    { int _o = soff[(KIDX) + 2];                                             \
      FA.x = 0ULL; FA.y = 0ULL; FB = FA;                                     \
      if (_o >= 0) { const ulonglong2* _p = (const ulonglong2*)(gA + _o);    \
          FA = _p[0]; FB = _p[1]; } }                                        \
    const ulonglong2* wp = (const ulonglong2*)(Wd + (size_t)(KIDX) * 8);     \
    ulonglong2 wA = wp[0], wB = wp[1], wC = wp[2], wD = wp[3];               \
    CH8(acc[0], a01.x); CH8(acc[1], a01.y);                                  \
    CH8(acc[2], a23.x); CH8(acc[3], a23.y);                                  \
} while (0)
#pragma unroll 2
    for (int k = 0; k < 64; k += 2) { LCB3(f0a, f0b, k); LCB3(f1a, f1b, k + 1); }
#pragma unroll
    for (int o = 0; o < 8; ++o) {
        const float bvv = lcb[o * 66 + loc] + biasc[o];
        float v[8];
#pragma unroll
        for (int p = 0; p < 4; ++p) UNPK(v[2 * p], v[2 * p + 1], acc[p][o]);
#pragma unroll
        for (int p = 0; p < 8; ++p) v[p] = lrelu(v[p] + bvv);
        float* dst = g_y2 + ((size_t)o * 66 + loc) * B_TOTAL + B0 + t * 8;
        ((float4*)dst)[0] = make_float4(v[0], v[1], v[2], v[3]);
        ((float4*)dst)[1] = make_float4(v[4], v[5], v[6], v[7]);
        float s = wsum(v[0]+v[1]+v[2]+v[3]+v[4]+v[5]+v[6]+v[7]);
        float q = wsum(v[0]*v[0]+v[1]*v[1]+v[2]*v[2]+v[3]*v[3]
                     + v[4]*v[4]+v[5]*v[5]+v[6]*v[6]+v[7]*v[7]);
        if ((t & 31) == 0) { atomicAdd(&red[o * 2], s); atomicAdd(&red[o * 2 + 1], q); }
    }
    __syncthreads();
    if (t < 16) g_part2[(blockIdx.y * 66 + loc) * 16 + t] = red[t];
}

// ============================ K5: BN2(folded) + pad + LC3 (R4) ================
__global__ void __launch_bounds__(128, 4) k5_lc3(const float* __restrict__ lcw,
                                                 const float* __restrict__ lcb) {
    __shared__ __align__(16) u64 Wd[256];
    __shared__ float biasc[8];
    __shared__ int soff[36];
    __shared__ float red[16];
    const int t = threadIdx.x, loc = blockIdx.x, B0 = blockIdx.y * 1024;
    const int h3 = loc >> 2, w3 = loc & 3;
#pragma unroll
    for (int rr = 0; rr < 2; ++rr) {
        int idx = rr * 128 + t;
        int o = idx & 7, k = idx >> 3, c = k >> 2;
        float wv = lcw[(size_t)((o * 8 + c) * 48 + loc) * 4 + (k & 3)];
        Wd[idx] = dup2f(wv * g_bnA2[c]);
    }
    for (int k = t; k < 36; k += 128) {
        int v = -1;
        if (k < 32) {
            int c = k >> 2, mm = k & 3;
            int hp = h3 + (mm >> 1), wp = 2 * w3 + (mm & 1);
            if (hp >= 1 && hp <= 11 && wp >= 1 && wp <= 6)
                v = (c * 66 + (hp - 1) * 6 + (wp - 1)) * B_TOTAL;
        }
        soff[k] = v;
    }
    if (t < 16) red[t] = 0.f;
    if (t < 8) {
        float s = 0.f;
#pragma unroll 1
        for (int k = 0; k < 32; ++k) {
            int c = k >> 2, mm = k & 3;
            int hp = h3 + (mm >> 1), wp = 2 * w3 + (mm & 1);
            if (hp >= 1 && hp <= 11 && wp >= 1 && wp <= 6)
                s += lcw[(size_t)((t * 8 + c) * 48 + loc) * 4 + mm] * g_bnB2[c];
        }
        biasc[t] = s;
    }
    __syncthreads();
    const float* gA = g_y2 + B0 + t * 8;
    u64 acc[4][8] = {};
    ulonglong2 f0a, f0b, f1a, f1b;
    f0a.x = f0a.y = 0ULL; f0b = f0a; f1a = f0a; f1b = f0a;
    if (soff[0] >= 0) { const ulonglong2* p = (const ulonglong2*)(gA + soff[0]); f0a = p[0]; f0b = p[1]; }
    if (soff[1] >= 0) { const ulonglong2* p = (const ulonglong2*)(gA + soff[1]); f1a = p[0]; f1b = p[1]; }
#pragma unroll 2
    for (int k = 0; k < 32; k += 2) { LCB3(f0a, f0b, k); LCB3(f1a, f1b, k + 1); }
#pragma unroll
    for (int o = 0; o < 8; ++o) {
        const float bvv = lcb[o * 48 + loc] + biasc[o];
        float v[8];
#pragma unroll
        for (int p = 0; p < 4; ++p) UNPK(v[2 * p], v[2 * p + 1], acc[p][o]);
#pragma unroll
        for (int p = 0; p < 8; ++p) v[p] = lrelu(v[p] + bvv);
        float* dst = g_y3 + ((size_t)o * 48 + loc) * B_TOTAL + B0 + t * 8;
        ((float4*)dst)[0] = make_float4(v[0], v[1], v[2], v[3]);
        ((float4*)dst)[1] = make_float4(v[4], v[5], v[6], v[7]);
        float s = wsum(v[0]+v[1]+v[2]+v[3]+v[4]+v[5]+v[6]+v[7]);
        float q = wsum(v[0]*v[0]+v[1]*v[1]+v[2]*v[2]+v[3]*v[3]
                     + v[4]*v[4]+v[5]*v[5]+v[6]*v[6]+v[7]*v[7]);
        if ((t & 31) == 0) { atomicAdd(&red[o * 2], s); atomicAdd(&red[o * 2 + 1], q); }
    }
    __syncthreads();
    if (t < 16) g_part3[(blockIdx.y * 48 + loc) * 16 + t] = red[t];
}

// ============================ stat reducer ====================================
__global__ void kred(int stage, int nb, int nch, float invN,
                     const float* __restrict__ gamma, const float* __restrict__ beta) {
    __shared__ float sm[1024];
    const float* part = (stage == 0) ? g_part1 : (stage == 1) ? g_part2 : g_part3;
    float* bnA = (stage == 0) ? g_bnA1 : (stage == 1) ? g_bnA2 : g_bnA3;
    float* bnB = (stage == 0) ? g_bnB1 : (stage == 1) ? g_bnB2 : g_bnB3;
    const int t = threadIdx.x;
    const int slots = 2 * nch;
    const int grp = t % slots, lane = t / slots, per = blockDim.x / slots;
    float s = 0.f;
    for (int i = lane; i < nb; i += per) s += part[i * slots + grp];
    sm[t] = s;
    __syncthreads();
    for (int step = per >> 1; step > 0; step >>= 1) {
        if (lane < step) sm[t] += sm[t + step * slots];
        __syncthreads();
    }
    if (t < nch) {
        float sum = sm[t * 2], sq = sm[t * 2 + 1];
        float mean = sum * invN;
        float var = sq * invN - mean * mean;
        float rs = rsqrtf(var + BN_EPS);
        float gg = gamma[t];
        bnA[t] = gg * rs;
        bnB[t] = beta[t] - mean * gg * rs;
    }
}

// ============================ K7: BN3 + transpose to output ===================
__global__ void k7_out(float* __restrict__ out) {
    __shared__ float tile[32][65];
    __shared__ float a3[8], b3[8];
    const int t = threadIdx.x;
    const int f0 = blockIdx.x * 32, b0 = blockIdx.y * 64;
    if (t < 8) { a3[t] = g_bnA3[t]; b3[t] = g_bnB3[t]; }
    __syncthreads();
#pragma unroll
    for (int r = 0; r < 8; ++r) {
        int f = r * 4 + (t >> 6), b = t & 63;
        float v = g_y3[(size_t)(f0 + f) * B_TOTAL + b0 + b];
        int c = (f0 + f) / 48;
        tile[f][b] = fmaf(a3[c], v, b3[c]);
    }
    __syncthreads();
#pragma unroll
    for (int r = 0; r < 8; ++r) {
        int f = t & 31, b = r * 8 + (t >> 5);
        out[(size_t)(b0 + b) * 384 + f0 + f] = tile[f][b];
    }
}

// ============================ launch ==========================================
extern "C" void kernel_launch(void* const* d_in, const int* in_sizes, int n_in,
                              void* d_out, int out_size) {
    const float* image = (const float*)d_in[0];
    const float* c1w   = (const float*)d_in[1];
    const float* c1b   = (const float*)d_in[2];
    const float* lc1w  = (const float*)d_in[3];
    const float* lc1b  = (const float*)d_in[4];
    const float* lc2w  = (const float*)d_in[5];
    const float* lc2b  = (const float*)d_in[6];
    const float* lc3w  = (const float*)d_in[7];
    const float* lc3b  = (const float*)d_in[8];
    const float* g1    = (const float*)d_in[9];
    const float* be1   = (const float*)d_in[10];
    const float* g2    = (const float*)d_in[11];
    const float* be2   = (const float*)d_in[12];
    const float* g3    = (const float*)d_in[13];
    const float* be3   = (const float*)d_in[14];
    float* out = (float*)d_out;

    cudaFuncSetAttribute(k0_conv1, cudaFuncAttributeMaxDynamicSharedMemorySize, SMEM0);
    cudaFuncSetAttribute(k1_mma,   cudaFuncAttributeMaxDynamicSharedMemorySize, K1SM);

    k0_conv1<<<dim3(32, 8),  256, SMEM0>>>(image, c1w, c1b);
    k1_mma  <<<dim3(50, 16), 256, K1SM>>>(lc1w, lc1b);
    kred    <<<1, 1024>>>(0, 800, 16, 1.0f / (8192.0f * 50.0f), g1, be1);
    k3_lc2  <<<dim3(66, 8),  128>>>(lc2w, lc2b);
    kred    <<<1, 1024>>>(1, 528, 8, 1.0f / (8192.0f * 66.0f), g2, be2);
    k5_lc3  <<<dim3(48, 8),  128>>>(lc3w, lc3b);
    kred    <<<1, 1024>>>(2, 384, 8, 1.0f / (8192.0f * 48.0f), g3, be3);
    k7_out  <<<dim3(12, 128), 256>>>(out);
}

// round 13
// speedup vs baseline: 1.3363x; 1.1756x over previous
#include <cuda_runtime.h>
#include <cstdint>

#define B_TOTAL   8192
#define LEAK      0.01f
#define BN_EPS    1e-5f

__device__ float g_conv[64 * 90 * B_TOTAL];   // conv1 out [64][10][9][B]
__device__ float g_y1[16 * 50 * B_TOTAL];
__device__ float g_y2[8 * 66 * B_TOTAL];
__device__ float g_y3[8 * 48 * B_TOTAL];
__device__ float g_part1[400 * 32];
__device__ float g_part2[528 * 16];
__device__ float g_part3[384 * 16];
__device__ float g_bnA1[16], g_bnB1[16];
__device__ float g_bnA2[8],  g_bnB2[8];
__device__ float g_bnA3[8],  g_bnB3[8];

typedef unsigned long long u64;

__device__ __forceinline__ float lrelu(float v) { return v < 0.f ? LEAK * v : v; }
__device__ __forceinline__ float wsum(float v) {
#pragma unroll
    for (int s = 16; s; s >>= 1) v += __shfl_xor_sync(0xffffffffu, v, s);
    return v;
}
__device__ __forceinline__ u64 dup2f(float v) {
    u64 r; asm("mov.b64 %0, {%1, %1};" : "=l"(r) : "f"(v)); return r;
}
#define FMA2(d, a, b)   asm("fma.rn.f32x2 %0, %1, %2, %0;" : "+l"(d) : "l"(a), "l"(b))
#define UNPK(lo, hi, v) asm("mov.b64 {%0, %1}, %2;" : "=f"(lo), "=f"(hi) : "l"(v))

#define CH8(ar, s)                                              \
    FMA2(ar[0], s, wA.x); FMA2(ar[1], s, wA.y);                 \
    FMA2(ar[2], s, wB.x); FMA2(ar[3], s, wB.y);                 \
    FMA2(ar[4], s, wC.x); FMA2(ar[5], s, wC.y);                 \
    FMA2(ar[6], s, wD.x); FMA2(ar[7], s, wD.y);

// ============================ K0: conv1 + lrelu ===============================
#define SMEM0 ((256 * 91 + 32 + 8) * 4)
__global__ void k0_conv1(const float* __restrict__ img,
                         const float* __restrict__ w1,
                         const float* __restrict__ b1) {
    extern __shared__ float sm0[];
    float* simg = sm0;
    float* sw   = sm0 + 256 * 91;
    float* sb   = sw + 32;
    const int t  = threadIdx.x;
    const int B0 = blockIdx.x * 256;
    const int c0 = blockIdx.y * 8;

#pragma unroll 1
    for (int i = 0; i < 90; ++i) {
        int f = i * 256 + t;
        int s = f / 90, off = f - s * 90;
        simg[s * 91 + off] = img[(B0 + s) * 90 + off];
    }
    if (t < 32) sw[t] = w1[c0 * 4 + t];
    if (t < 8)  sb[t] = b1[c0 + t];
    __syncthreads();

    const int q  = t & 63;
    const int cg = t >> 6;
    float W00[2], W01[2], W10[2], W11[2], BB[2];
#pragma unroll
    for (int c2 = 0; c2 < 2; ++c2) {
        int cc = cg * 2 + c2;
        W00[c2] = sw[cc * 4 + 0]; W01[c2] = sw[cc * 4 + 1];
        W10[c2] = sw[cc * 4 + 2]; W11[c2] = sw[cc * 4 + 3];
        BB[c2]  = sb[cc];
    }

#pragma unroll 1
    for (int h = 0; h < 10; ++h) {
        float a[4][9], b[4][9];
        const bool hb = (h < 9);
#pragma unroll
        for (int s = 0; s < 4; ++s) {
            const float* rp = simg + (q * 4 + s) * 91 + h * 9;
#pragma unroll
            for (int w = 0; w < 9; ++w) {
                a[s][w] = rp[w];
                b[s][w] = hb ? rp[9 + w] : 0.f;
            }
        }
#pragma unroll
        for (int c2 = 0; c2 < 2; ++c2) {
            const int c = c0 + cg * 2 + c2;
            float* op = g_conv + ((size_t)c * 90 + h * 9) * B_TOTAL + B0 + q * 4;
            const float w00 = W00[c2], w01 = W01[c2], w10 = W10[c2], w11 = W11[c2], bv = BB[c2];
#pragma unroll
            for (int w = 0; w < 9; ++w) {
                float v[4];
#pragma unroll
                for (int s = 0; s < 4; ++s) {
                    float t0 = fmaf(a[s][w], w00, bv);
                    if (w < 8) t0 = fmaf(a[s][w + 1], w01, t0);
                    t0 = fmaf(b[s][w], w10, t0);
                    if (w < 8) t0 = fmaf(b[s][w + 1], w11, t0);
                    v[s] = lrelu(t0);
                }
                ((float4*)(op + (size_t)w * B_TOTAL))[0] = make_float4(v[0], v[1], v[2], v[3]);
            }
        }
    }
}

// ============================ K1: LC1 compacted, intra-kernel dispatch ========
// Thread: 4 samples x 16 ch. NV = NIJ*64 compile-time per branch.
#define K1_BODY(PF, KIDX) do {                                               \
    float4 cur = PF;                                                         \
    PF = *(const float4*)(gA + soff[(KIDX) + 4]);                            \
    u64 s0 = dup2f(cur.x), s1 = dup2f(cur.y);                                \
    u64 s2 = dup2f(cur.z), s3 = dup2f(cur.w);                                \
    const ulonglong2* wp = Wv + (size_t)(KIDX) * 4;                          \
    ulonglong2 wA = wp[0], wB = wp[1], wC = wp[2], wD = wp[3];               \
    CH8(acc[0], s0); CH8(acc[1], s1); CH8(acc[2], s2); CH8(acc[3], s3);      \
} while (0)

template<int NIJ>
__device__ __forceinline__ void k1_body(
    int t, int loc, int h, int w, int B0, int by,
    const float* __restrict__ lcw, const float* __restrict__ lcb,
    float* Wsm, int* soff, float* red, int* smi, int* smj) {
    constexpr int NV = NIJ * 64;

    const int i3lo = (h == 0) ? 1 : 0;
    const int j3lo = (w == 0) ? 1 : 0;
    const int nJ = (w == 0 || w == 4) ? 2 : 3;
    if (t < NIJ) { smi[t] = i3lo + t / nJ; smj[t] = j3lo + t - (t / nJ) * nJ; }
    if (t < 32) red[t] = 0.f;
    __syncthreads();

#pragma unroll
    for (int rr = 0; rr < 4; ++rr) {
        int rid = rr * 256 + t;
        int o = rid >> 6, c = rid & 63;
        const float* src = lcw + ((size_t)(o * 64 + c) * 50 + loc) * 9;
#pragma unroll
        for (int m = 0; m < NIJ; ++m)
            Wsm[((m << 6) + c) * 16 + o] = src[smi[m] * 3 + smj[m]];
    }
    for (int kk = t; kk < NV + 4; kk += 256) {
        int v = 0;
        if (kk < NV) {
            int c = kk & 63, m = kk >> 6;
            v = ((c * 10 + h + smi[m] - 1) * 9 + (2 * w + smj[m] - 1)) * B_TOTAL;
        }
        soff[kk] = v;
    }
    __syncthreads();

    const float* gA = g_conv + B0 + t * 4;
    const ulonglong2* Wv = (const ulonglong2*)Wsm;
    u64 acc[4][8] = {};

    float4 pf0 = *(const float4*)(gA + soff[0]);
    float4 pf1 = *(const float4*)(gA + soff[1]);
    float4 pf2 = *(const float4*)(gA + soff[2]);
    float4 pf3 = *(const float4*)(gA + soff[3]);

#pragma unroll 4
    for (int k = 0; k < NV; k += 4) {
        K1_BODY(pf0, k);
        K1_BODY(pf1, k + 1);
        K1_BODY(pf2, k + 2);
        K1_BODY(pf3, k + 3);
    }

#pragma unroll
    for (int j = 0; j < 8; ++j) {
        const int o0 = 2 * j, o1 = 2 * j + 1;
        const float b0v = lcb[o0 * 50 + loc];
        const float b1v = lcb[o1 * 50 + loc];
        float lo[4], hi[4];
#pragma unroll
        for (int s = 0; s < 4; ++s) UNPK(lo[s], hi[s], acc[s][j]);
        float a0 = lrelu(lo[0] + b0v), a1 = lrelu(lo[1] + b0v);
        float a2 = lrelu(lo[2] + b0v), a3 = lrelu(lo[3] + b0v);
        float c0 = lrelu(hi[0] + b1v), c1 = lrelu(hi[1] + b1v);
        float c2 = lrelu(hi[2] + b1v), c3 = lrelu(hi[3] + b1v);
        ((float4*)(g_y1 + ((size_t)o0 * 50 + loc) * B_TOTAL + B0))[t] = make_float4(a0, a1, a2, a3);
        ((float4*)(g_y1 + ((size_t)o1 * 50 + loc) * B_TOTAL + B0))[t] = make_float4(c0, c1, c2, c3);
        float s0 = wsum(a0 + a1 + a2 + a3), q0 = wsum(a0*a0 + a1*a1 + a2*a2 + a3*a3);
        float s1 = wsum(c0 + c1 + c2 + c3), q1 = wsum(c0*c0 + c1*c1 + c2*c2 + c3*c3);
        if ((t & 31) == 0) {
            atomicAdd(&red[o0 * 2 + 0], s0); atomicAdd(&red[o0 * 2 + 1], q0);
            atomicAdd(&red[o1 * 2 + 0], s1); atomicAdd(&red[o1 * 2 + 1], q1);
        }
    }
    __syncthreads();
    if (t < 32) g_part1[(by * 50 + loc) * 32 + t] = red[t];
}

__global__ void __launch_bounds__(256, 2) k1_lc1(const float* __restrict__ lcw,
                                                 const float* __restrict__ lcb) {
    __shared__ __align__(16) float Wsm[9216];
    __shared__ int soff[580];
    __shared__ float red[32];
    __shared__ int smi[9], smj[9];
    const int t   = threadIdx.x;
    const int loc = blockIdx.x;
    const int B0  = blockIdx.y * 1024;
    const int h = loc / 5, w = loc - h * 5;
    const int nI = (h == 0 || h == 9) ? 2 : 3;
    const int nJ = (w == 0 || w == 4) ? 2 : 3;
    const int nIJ = nI * nJ;
    if (nIJ == 9)      k1_body<9>(t, loc, h, w, B0, blockIdx.y, lcw, lcb, Wsm, soff, red, smi, smj);
    else if (nIJ == 6) k1_body<6>(t, loc, h, w, B0, blockIdx.y, lcw, lcb, Wsm, soff, red, smi, smj);
    else               k1_body<4>(t, loc, h, w, B0, blockIdx.y, lcw, lcb, Wsm, soff, red, smi, smj);
}

// ============================ K3/K5 common body ===============================
#define LC_BODY(FA, FB, KIDX) do {                                           \
    ulonglong2 a01 = FA, a23 = FB;                                           \
    { const ulonglong2* _p = (const ulonglong2*)(gA + soff[(KIDX) + 2]);     \
      FA = _p[0]; FB = _p[1]; }                                              \
    const ulonglong2* wp = (const ulonglong2*)(Wd + (size_t)(KIDX) * 8);     \
    ulonglong2 wA = wp[0], wB = wp[1], wC = wp[2], wD = wp[3];               \
    CH8(acc[0], a01.x); CH8(acc[1], a01.y);                                  \
    CH8(acc[2], a23.x); CH8(acc[3], a23.y);                                  \
} while (0)

// ============================ K3: BN1(folded) + LC2 ===========================
template<int NIJ>
__device__ __forceinline__ void k3_body(
    int t, int loc, int h2, int w2, int B0, int by,
    const float* __restrict__ lcw, const float* __restrict__ lcb,
    u64* Wd, float* biasc, int* soff, float* red, int* smi, int* smj) {
    constexpr int NV = NIJ * 16;

    const int ilo = (h2 == 0) ? 1 : 0;
    const int jlo = (w2 == 0) ? 1 : 0;
    const int nJ = (w2 == 0 || w2 == 5) ? 1 : 2;
    if (t < NIJ) { smi[t] = ilo + t / nJ; smj[t] = jlo + t - (t / nJ) * nJ; }
    if (t < 16) red[t] = 0.f;
    __syncthreads();

#pragma unroll
    for (int ff = 0; ff < NV * 8; ff += 128) {
        int f = ff + t;
        int kk = f >> 3, o = f & 7;
        int c = kk & 15, m = kk >> 4;
        float wv = lcw[(size_t)((o * 16 + c) * 66 + loc) * 4 + smi[m] * 2 + smj[m]];
        Wd[f] = dup2f(wv * g_bnA1[c]);
    }
    for (int kk = t; kk < NV + 2; kk += 128) {
        int v = 0;
        if (kk < NV) {
            int c = kk & 15, m = kk >> 4;
            v = (c * 50 + (h2 + smi[m] - 1) * 5 + (w2 + smj[m] - 1)) * B_TOTAL;
        }
        soff[kk] = v;
    }
    if (t < 8) {
        float s = 0.f;
#pragma unroll
        for (int kk = 0; kk < NV; ++kk) {
            int c = kk & 15, m = kk >> 4;
            s += lcw[(size_t)((t * 16 + c) * 66 + loc) * 4 + smi[m] * 2 + smj[m]] * g_bnB1[c];
        }
        biasc[t] = s;
    }
    __syncthreads();

    const float* gA = g_y1 + B0 + t * 8;
    u64 acc[4][8] = {};
    ulonglong2 f0a, f0b, f1a, f1b;
    { const ulonglong2* p = (const ulonglong2*)(gA + soff[0]); f0a = p[0]; f0b = p[1]; }
    { const ulonglong2* p = (const ulonglong2*)(gA + soff[1]); f1a = p[0]; f1b = p[1]; }

#pragma unroll 4
    for (int k = 0; k < NV; k += 2) {
        LC_BODY(f0a, f0b, k);
        LC_BODY(f1a, f1b, k + 1);
    }

#pragma unroll
    for (int o = 0; o < 8; ++o) {
        const float bv = lcb[o * 66 + loc] + biasc[o];
        float v[8];
#pragma unroll
        for (int p = 0; p < 4; ++p) UNPK(v[2 * p], v[2 * p + 1], acc[p][o]);
#pragma unroll
        for (int p = 0; p < 8; ++p) v[p] = lrelu(v[p] + bv);
        float* dst = g_y2 + ((size_t)o * 66 + loc) * B_TOTAL + B0 + t * 8;
        ((float4*)dst)[0] = make_float4(v[0], v[1], v[2], v[3]);
        ((float4*)dst)[1] = make_float4(v[4], v[5], v[6], v[7]);
        float s = wsum(v[0]+v[1]+v[2]+v[3]+v[4]+v[5]+v[6]+v[7]);
        float q = wsum(v[0]*v[0]+v[1]*v[1]+v[2]*v[2]+v[3]*v[3]
                     + v[4]*v[4]+v[5]*v[5]+v[6]*v[6]+v[7]*v[7]);
        if ((t & 31) == 0) {
            atomicAdd(&red[o * 2 + 0], s);
            atomicAdd(&red[o * 2 + 1], q);
        }
    }
    __syncthreads();
    if (t < 16) g_part2[(by * 66 + loc) * 16 + t] = red[t];
}

__global__ void __launch_bounds__(128, 4) k3_lc2(const float* __restrict__ lcw,
                                                 const float* __restrict__ lcb) {
    __shared__ __align__(16) u64 Wd[512];
    __shared__ float biasc[8];
    __shared__ int soff[66];
    __shared__ float red[16];
    __shared__ int smi[4], smj[4];
    const int t   = threadIdx.x;
    const int loc = blockIdx.x;
    const int B0  = blockIdx.y * 1024;
    const int h2 = loc / 6, w2 = loc - h2 * 6;
    const int nI = (h2 == 0 || h2 == 10) ? 1 : 2;
    const int nJ = (w2 == 0 || w2 == 5) ? 1 : 2;
    const int nIJ = nI * nJ;
    if (nIJ == 4)      k3_body<4>(t, loc, h2, w2, B0, blockIdx.y, lcw, lcb, Wd, biasc, soff, red, smi, smj);
    else if (nIJ == 2) k3_body<2>(t, loc, h2, w2, B0, blockIdx.y, lcw, lcb, Wd, biasc, soff, red, smi, smj);
    else               k3_body<1>(t, loc, h2, w2, B0, blockIdx.y, lcw, lcb, Wd, biasc, soff, red, smi, smj);
}

// ============================ K5: BN2(folded) + LC3 ===========================
template<int NIJ>
__device__ __forceinline__ void k5_body(
    int t, int loc, int h3, int w3, int B0, int by,
    const float* __restrict__ lcw, const float* __restrict__ lcb,
    u64* Wd, float* biasc, int* soff, float* red, int* smi, int* smj) {
    constexpr int NV = NIJ * 8;

    const int ilo = (h3 == 0) ? 1 : 0;
    const int jlo = (w3 == 0) ? 1 : 0;
    const int nJ = (w3 == 0 || w3 == 3) ? 1 : 2;
    if (t < NIJ) { smi[t] = ilo + t / nJ; smj[t] = jlo + t - (t / nJ) * nJ; }
    if (t < 16) red[t] = 0.f;
    __syncthreads();

    {
        int f = t;
        if (f < NV * 8) {
            int kk = f >> 3, o = f & 7;
            int c = kk & 7, m = kk >> 3;
            float wv = lcw[(size_t)((o * 8 + c) * 48 + loc) * 4 + smi[m] * 2 + smj[m]];
            Wd[f] = dup2f(wv * g_bnA2[c]);
        }
        if (NV * 8 > 128) {
            f = 128 + t;
            if (f < NV * 8) {
                int kk = f >> 3, o = f & 7;
                int c = kk & 7, m = kk >> 3;
                float wv = lcw[(size_t)((o * 8 + c) * 48 + loc) * 4 + smi[m] * 2 + smj[m]];
                Wd[f] = dup2f(wv * g_bnA2[c]);
            }
        }
    }
    for (int kk = t; kk < NV + 2; kk += 128) {
        int v = 0;
        if (kk < NV) {
            int c = kk & 7, m = kk >> 3;
            v = (c * 66 + (h3 + smi[m] - 1) * 6 + (2 * w3 + smj[m] - 1)) * B_TOTAL;
        }
        soff[kk] = v;
    }
    if (t < 8) {
        float s = 0.f;
#pragma unroll
        for (int kk = 0; kk < NV; ++kk) {
            int c = kk & 7, m = kk >> 3;
            s += lcw[(size_t)((t * 8 + c) * 48 + loc) * 4 + smi[m] * 2 + smj[m]] * g_bnB2[c];
        }
        biasc[t] = s;
    }
    __syncthreads();

    const float* gA = g_y2 + B0 + t * 8;
    u64 acc[4][8] = {};
    ulonglong2 f0a, f0b, f1a, f1b;
    { const ulonglong2* p = (const ulonglong2*)(gA + soff[0]); f0a = p[0]; f0b = p[1]; }
    { const ulonglong2* p = (const ulonglong2*)(gA + soff[1]); f1a = p[0]; f1b = p[1]; }

#pragma unroll 4
    for (int k = 0; k < NV; k += 2) {
        LC_BODY(f0a, f0b, k);
        LC_BODY(f1a, f1b, k + 1);
    }

#pragma unroll
    for (int o = 0; o < 8; ++o) {
        const float bv = lcb[o * 48 + loc] + biasc[o];
        float v[8];
#pragma unroll
        for (int p = 0; p < 4; ++p) UNPK(v[2 * p], v[2 * p + 1], acc[p][o]);
#pragma unroll
        for (int p = 0; p < 8; ++p) v[p] = lrelu(v[p] + bv);
        float* dst = g_y3 + ((size_t)o * 48 + loc) * B_TOTAL + B0 + t * 8;
        ((float4*)dst)[0] = make_float4(v[0], v[1], v[2], v[3]);
        ((float4*)dst)[1] = make_float4(v[4], v[5], v[6], v[7]);
        float s = wsum(v[0]+v[1]+v[2]+v[3]+v[4]+v[5]+v[6]+v[7]);
        float q = wsum(v[0]*v[0]+v[1]*v[1]+v[2]*v[2]+v[3]*v[3]
                     + v[4]*v[4]+v[5]*v[5]+v[6]*v[6]+v[7]*v[7]);
        if ((t & 31) == 0) {
            atomicAdd(&red[o * 2 + 0], s);
            atomicAdd(&red[o * 2 + 1], q);
        }
    }
    __syncthreads();
    if (t < 16) g_part3[(by * 48 + loc) * 16 + t] = red[t];
}

__global__ void __launch_bounds__(128, 4) k5_lc3(const float* __restrict__ lcw,
                                                 const float* __restrict__ lcb) {
    __shared__ __align__(16) u64 Wd[256];
    __shared__ float biasc[8];
    __shared__ int soff[34];
    __shared__ float red[16];
    __shared__ int smi[4], smj[4];
    const int t   = threadIdx.x;
    const int loc = blockIdx.x;
    const int B0  = blockIdx.y * 1024;
    const int h3 = loc >> 2, w3 = loc & 3;
    const int nI = (h3 == 0 || h3 == 11) ? 1 : 2;
    const int nJ = (w3 == 0 || w3 == 3) ? 1 : 2;
    const int nIJ = nI * nJ;
    if (nIJ == 4)      k5_body<4>(t, loc, h3, w3, B0, blockIdx.y, lcw, lcb, Wd, biasc, soff, red, smi, smj);
    else if (nIJ == 2) k5_body<2>(t, loc, h3, w3, B0, blockIdx.y, lcw, lcb, Wd, biasc, soff, red, smi, smj);
    else               k5_body<1>(t, loc, h3, w3, B0, blockIdx.y, lcw, lcb, Wd, biasc, soff, red, smi, smj);
}

// ============================ stat reducer ====================================
__global__ void kred(int stage, int nb, int nch, float invN,
                     const float* __restrict__ gamma, const float* __restrict__ beta) {
    __shared__ float sm[1024];
    const float* part = (stage == 0) ? g_part1 : (stage == 1) ? g_part2 : g_part3;
    float* bnA = (stage == 0) ? g_bnA1 : (stage == 1) ? g_bnA2 : g_bnA3;
    float* bnB = (stage == 0) ? g_bnB1 : (stage == 1) ? g_bnB2 : g_bnB3;
    const int t = threadIdx.x;
    const int slots = 2 * nch;
    const int grp = t % slots;
    const int lane = t / slots;
    const int per = blockDim.x / slots;
    float s = 0.f;
    for (int i = lane; i < nb; i += per) s += part[i * slots + grp];
    sm[t] = s;
    __syncthreads();
    for (int step = per >> 1; step > 0; step >>= 1) {
        if (lane < step) sm[t] += sm[t + step * slots];
        __syncthreads();
    }
    if (t < nch) {
        float sum = sm[t * 2 + 0], sq = sm[t * 2 + 1];
        float mean = sum * invN;
        float var = sq * invN - mean * mean;
        float rs = rsqrtf(var + BN_EPS);
        float g = gamma[t];
        bnA[t] = g * rs;
        bnB[t] = beta[t] - mean * g * rs;
    }
}

// ============================ K7: BN3 + transpose to output ===================
__global__ void k7_out(float* __restrict__ out) {
    __shared__ float tile[32][65];
    __shared__ float a3[8], b3[8];
    const int t  = threadIdx.x;
    const int f0 = blockIdx.x * 32;
    const int b0 = blockIdx.y * 64;
    if (t < 8) { a3[t] = g_bnA3[t]; b3[t] = g_bnB3[t]; }
    __syncthreads();
#pragma unroll
    for (int r = 0; r < 8; ++r) {
        int f = r * 4 + (t >> 6);
        int b = t & 63;
        float v = g_y3[(size_t)(f0 + f) * B_TOTAL + b0 + b];
        int c = (f0 + f) / 48;
        tile[f][b] = fmaf(a3[c], v, b3[c]);
    }
    __syncthreads();
#pragma unroll
    for (int r = 0; r < 8; ++r) {
        int f = t & 31;
        int b = r * 8 + (t >> 5);
        out[(size_t)(b0 + b) * 384 + f0 + f] = tile[f][b];
    }
}

// ============================ launch ==========================================
extern "C" void kernel_launch(void* const* d_in, const int* in_sizes, int n_in,
                              void* d_out, int out_size) {
    const float* image = (const float*)d_in[0];
    const float* c1w   = (const float*)d_in[1];
    const float* c1b   = (const float*)d_in[2];
    const float* lc1w  = (const float*)d_in[3];
    const float* lc1b  = (const float*)d_in[4];
    const float* lc2w  = (const float*)d_in[5];
    const float* lc2b  = (const float*)d_in[6];
    const float* lc3w  = (const float*)d_in[7];
    const float* lc3b  = (const float*)d_in[8];
    const float* g1    = (const float*)d_in[9];
    const float* be1   = (const float*)d_in[10];
    const float* g2    = (const float*)d_in[11];
    const float* be2   = (const float*)d_in[12];
    const float* g3    = (const float*)d_in[13];
    const float* be3   = (const float*)d_in[14];
    float* out = (float*)d_out;

    cudaFuncSetAttribute(k0_conv1, cudaFuncAttributeMaxDynamicSharedMemorySize, SMEM0);

    k0_conv1<<<dim3(32, 8), 256, SMEM0>>>(image, c1w, c1b);
    k1_lc1  <<<dim3(50, 8), 256>>>(lc1w, lc1b);
    kred    <<<1, 1024>>>(0, 400, 16, 1.0f / (8192.0f * 50.0f), g1, be1);
    k3_lc2  <<<dim3(66, 8), 128>>>(lc2w, lc2b);
    kred    <<<1, 1024>>>(1, 528, 8, 1.0f / (8192.0f * 66.0f), g2, be2);
    k5_lc3  <<<dim3(48, 8), 128>>>(lc3w, lc3b);
    kred    <<<1, 1024>>>(2, 384, 8, 1.0f / (8192.0f * 48.0f), g3, be3);
    k7_out  <<<dim3(12, 128), 256>>>(out);
}

// round 14
// speedup vs baseline: 1.3475x; 1.0083x over previous
#include <cuda_runtime.h>
#include <cstdint>

#define B_TOTAL   8192
#define LEAK      0.01f
#define BN_EPS    1e-5f

__device__ float g_conv[64 * 90 * B_TOTAL];   // conv1 out [64][10][9][B]
__device__ float g_y1[16 * 50 * B_TOTAL];
__device__ float g_y2[8 * 66 * B_TOTAL];
__device__ float g_y3[8 * 48 * B_TOTAL];
__device__ float g_part1[400 * 32];
__device__ float g_part2[528 * 16];
__device__ float g_part3[384 * 16];
__device__ float g_bnA1[16], g_bnB1[16];
__device__ float g_bnA2[8],  g_bnB2[8];
__device__ float g_bnA3[8],  g_bnB3[8];

typedef unsigned long long u64;

__device__ __forceinline__ float lrelu(float v) { return v < 0.f ? LEAK * v : v; }
__device__ __forceinline__ float wsum(float v) {
#pragma unroll
    for (int s = 16; s; s >>= 1) v += __shfl_xor_sync(0xffffffffu, v, s);
    return v;
}
__device__ __forceinline__ u64 dup2f(float v) {
    u64 r; asm("mov.b64 %0, {%1, %1};" : "=l"(r) : "f"(v)); return r;
}
#define FMA2(d, a, b)   asm("fma.rn.f32x2 %0, %1, %2, %0;" : "+l"(d) : "l"(a), "l"(b))
#define UNPK(lo, hi, v) asm("mov.b64 {%0, %1}, %2;" : "=f"(lo), "=f"(hi) : "l"(v))

#define CH8(ar, s)                                              \
    FMA2(ar[0], s, wA.x); FMA2(ar[1], s, wA.y);                 \
    FMA2(ar[2], s, wB.x); FMA2(ar[3], s, wB.y);                 \
    FMA2(ar[4], s, wC.x); FMA2(ar[5], s, wC.y);                 \
    FMA2(ar[6], s, wD.x); FMA2(ar[7], s, wD.y);

// ============================ K0: conv1 + lrelu ===============================
#define SMEM0 ((256 * 91 + 32 + 8) * 4)
__global__ void k0_conv1(const float* __restrict__ img,
                         const float* __restrict__ w1,
                         const float* __restrict__ b1) {
    extern __shared__ float sm0[];
    float* simg = sm0;
    float* sw   = sm0 + 256 * 91;
    float* sb   = sw + 32;
    const int t  = threadIdx.x;
    const int B0 = blockIdx.x * 256;
    const int c0 = blockIdx.y * 8;

#pragma unroll 1
    for (int i = 0; i < 90; ++i) {
        int f = i * 256 + t;
        int s = f / 90, off = f - s * 90;
        simg[s * 91 + off] = img[(B0 + s) * 90 + off];
    }
    if (t < 32) sw[t] = w1[c0 * 4 + t];
    if (t < 8)  sb[t] = b1[c0 + t];
    __syncthreads();

    const int q  = t & 63;
    const int cg = t >> 6;
    float W00[2], W01[2], W10[2], W11[2], BB[2];
#pragma unroll
    for (int c2 = 0; c2 < 2; ++c2) {
        int cc = cg * 2 + c2;
        W00[c2] = sw[cc * 4 + 0]; W01[c2] = sw[cc * 4 + 1];
        W10[c2] = sw[cc * 4 + 2]; W11[c2] = sw[cc * 4 + 3];
        BB[c2]  = sb[cc];
    }

#pragma unroll 1
    for (int h = 0; h < 10; ++h) {
        float a[4][9], b[4][9];
        const bool hb = (h < 9);
#pragma unroll
        for (int s = 0; s < 4; ++s) {
            const float* rp = simg + (q * 4 + s) * 91 + h * 9;
#pragma unroll
            for (int w = 0; w < 9; ++w) {
                a[s][w] = rp[w];
                b[s][w] = hb ? rp[9 + w] : 0.f;
            }
        }
#pragma unroll
        for (int c2 = 0; c2 < 2; ++c2) {
            const int c = c0 + cg * 2 + c2;
            float* op = g_conv + ((size_t)c * 90 + h * 9) * B_TOTAL + B0 + q * 4;
            const float w00 = W00[c2], w01 = W01[c2], w10 = W10[c2], w11 = W11[c2], bv = BB[c2];
#pragma unroll
            for (int w = 0; w < 9; ++w) {
                float v[4];
#pragma unroll
                for (int s = 0; s < 4; ++s) {
                    float t0 = fmaf(a[s][w], w00, bv);
                    if (w < 8) t0 = fmaf(a[s][w + 1], w01, t0);
                    t0 = fmaf(b[s][w], w10, t0);
                    if (w < 8) t0 = fmaf(b[s][w + 1], w11, t0);
                    v[s] = lrelu(t0);
                }
                ((float4*)(op + (size_t)w * B_TOTAL))[0] = make_float4(v[0], v[1], v[2], v[3]);
            }
        }
    }
}

// ============================ K1: LC1 compacted, intra-kernel dispatch ========
// Thread: 4 samples x 16 ch. NV = NIJ*64 compile-time. Prefetch depth 8.
#define K1_BODY(PF, KIDX) do {                                               \
    float4 cur = PF;                                                         \
    PF = *(const float4*)(gA + soff[(KIDX) + 8]);                            \
    u64 s0 = dup2f(cur.x), s1 = dup2f(cur.y);                                \
    u64 s2 = dup2f(cur.z), s3 = dup2f(cur.w);                                \
    const ulonglong2* wp = Wv + (size_t)(KIDX) * 4;                          \
    ulonglong2 wA = wp[0], wB = wp[1], wC = wp[2], wD = wp[3];               \
    CH8(acc[0], s0); CH8(acc[1], s1); CH8(acc[2], s2); CH8(acc[3], s3);      \
} while (0)

template<int NIJ>
__device__ __forceinline__ void k1_body(
    int t, int loc, int h, int w, int B0, int by,
    const float* __restrict__ lcw, const float* __restrict__ lcb,
    float* Wsm, int* soff, float* red, int* smi, int* smj) {
    constexpr int NV = NIJ * 64;

    const int i3lo = (h == 0) ? 1 : 0;
    const int j3lo = (w == 0) ? 1 : 0;
    const int nJ = (w == 0 || w == 4) ? 2 : 3;
    if (t < NIJ) { smi[t] = i3lo + t / nJ; smj[t] = j3lo + t - (t / nJ) * nJ; }
    if (t < 32) red[t] = 0.f;
    __syncthreads();

#pragma unroll
    for (int rr = 0; rr < 4; ++rr) {
        int rid = rr * 256 + t;
        int o = rid >> 6, c = rid & 63;
        const float* src = lcw + ((size_t)(o * 64 + c) * 50 + loc) * 9;
#pragma unroll
        for (int m = 0; m < NIJ; ++m)
            Wsm[((m << 6) + c) * 16 + o] = src[smi[m] * 3 + smj[m]];
    }
    for (int kk = t; kk < NV + 8; kk += 256) {
        int v = 0;
        if (kk < NV) {
            int c = kk & 63, m = kk >> 6;
            v = ((c * 10 + h + smi[m] - 1) * 9 + (2 * w + smj[m] - 1)) * B_TOTAL;
        }
        soff[kk] = v;
    }
    __syncthreads();

    const float* gA = g_conv + B0 + t * 4;
    const ulonglong2* Wv = (const ulonglong2*)Wsm;
    u64 acc[4][8] = {};

    float4 pf0 = *(const float4*)(gA + soff[0]);
    float4 pf1 = *(const float4*)(gA + soff[1]);
    float4 pf2 = *(const float4*)(gA + soff[2]);
    float4 pf3 = *(const float4*)(gA + soff[3]);
    float4 pf4 = *(const float4*)(gA + soff[4]);
    float4 pf5 = *(const float4*)(gA + soff[5]);
    float4 pf6 = *(const float4*)(gA + soff[6]);
    float4 pf7 = *(const float4*)(gA + soff[7]);

#pragma unroll 2
    for (int k = 0; k < NV; k += 8) {
        K1_BODY(pf0, k);
        K1_BODY(pf1, k + 1);
        K1_BODY(pf2, k + 2);
        K1_BODY(pf3, k + 3);
        K1_BODY(pf4, k + 4);
        K1_BODY(pf5, k + 5);
        K1_BODY(pf6, k + 6);
        K1_BODY(pf7, k + 7);
    }

#pragma unroll
    for (int j = 0; j < 8; ++j) {
        const int o0 = 2 * j, o1 = 2 * j + 1;
        const float b0v = lcb[o0 * 50 + loc];
        const float b1v = lcb[o1 * 50 + loc];
        float lo[4], hi[4];
#pragma unroll
        for (int s = 0; s < 4; ++s) UNPK(lo[s], hi[s], acc[s][j]);
        float a0 = lrelu(lo[0] + b0v), a1 = lrelu(lo[1] + b0v);
        float a2 = lrelu(lo[2] + b0v), a3 = lrelu(lo[3] + b0v);
        float c0 = lrelu(hi[0] + b1v), c1 = lrelu(hi[1] + b1v);
        float c2 = lrelu(hi[2] + b1v), c3 = lrelu(hi[3] + b1v);
        ((float4*)(g_y1 + ((size_t)o0 * 50 + loc) * B_TOTAL + B0))[t] = make_float4(a0, a1, a2, a3);
        ((float4*)(g_y1 + ((size_t)o1 * 50 + loc) * B_TOTAL + B0))[t] = make_float4(c0, c1, c2, c3);
        float s0 = wsum(a0 + a1 + a2 + a3), q0 = wsum(a0*a0 + a1*a1 + a2*a2 + a3*a3);
        float s1 = wsum(c0 + c1 + c2 + c3), q1 = wsum(c0*c0 + c1*c1 + c2*c2 + c3*c3);
        if ((t & 31) == 0) {
            atomicAdd(&red[o0 * 2 + 0], s0); atomicAdd(&red[o0 * 2 + 1], q0);
            atomicAdd(&red[o1 * 2 + 0], s1); atomicAdd(&red[o1 * 2 + 1], q1);
        }
    }
    __syncthreads();
    if (t < 32) g_part1[(by * 50 + loc) * 32 + t] = red[t];
}

__global__ void __launch_bounds__(256, 2) k1_lc1(const float* __restrict__ lcw,
                                                 const float* __restrict__ lcb) {
    __shared__ __align__(16) float Wsm[9216];
    __shared__ int soff[584];
    __shared__ float red[32];
    __shared__ int smi[9], smj[9];
    const int t   = threadIdx.x;
    const int loc = blockIdx.x;
    const int B0  = blockIdx.y * 1024;
    const int h = loc / 5, w = loc - h * 5;
    const int nI = (h == 0 || h == 9) ? 2 : 3;
    const int nJ = (w == 0 || w == 4) ? 2 : 3;
    const int nIJ = nI * nJ;
    if (nIJ == 9)      k1_body<9>(t, loc, h, w, B0, blockIdx.y, lcw, lcb, Wsm, soff, red, smi, smj);
    else if (nIJ == 6) k1_body<6>(t, loc, h, w, B0, blockIdx.y, lcw, lcb, Wsm, soff, red, smi, smj);
    else               k1_body<4>(t, loc, h, w, B0, blockIdx.y, lcw, lcb, Wsm, soff, red, smi, smj);
}

// ============================ K3/K5 common body ===============================
#define LC_BODY(FA, FB, KIDX) do {                                           \
    ulonglong2 a01 = FA, a23 = FB;                                           \
    { const ulonglong2* _p = (const ulonglong2*)(gA + soff[(KIDX) + 2]);     \
      FA = _p[0]; FB = _p[1]; }                                              \
    const ulonglong2* wp = (const ulonglong2*)(Wd + (size_t)(KIDX) * 8);     \
    ulonglong2 wA = wp[0], wB = wp[1], wC = wp[2], wD = wp[3];               \
    CH8(acc[0], a01.x); CH8(acc[1], a01.y);                                  \
    CH8(acc[2], a23.x); CH8(acc[3], a23.y);                                  \
} while (0)

// ============================ K3: BN1(folded) + LC2 ===========================
template<int NIJ>
__device__ __forceinline__ void k3_body(
    int t, int loc, int h2, int w2, int B0, int by,
    const float* __restrict__ lcw, const float* __restrict__ lcb,
    u64* Wd, float* biasc, int* soff, float* red, int* smi, int* smj) {
    constexpr int NV = NIJ * 16;

    const int ilo = (h2 == 0) ? 1 : 0;
    const int jlo = (w2 == 0) ? 1 : 0;
    const int nJ = (w2 == 0 || w2 == 5) ? 1 : 2;
    if (t < NIJ) { smi[t] = ilo + t / nJ; smj[t] = jlo + t - (t / nJ) * nJ; }
    if (t < 16) red[t] = 0.f;
    __syncthreads();

#pragma unroll
    for (int ff = 0; ff < NV * 8; ff += 128) {
        int f = ff + t;
        int kk = f >> 3, o = f & 7;
        int c = kk & 15, m = kk >> 4;
        float wv = lcw[(size_t)((o * 16 + c) * 66 + loc) * 4 + smi[m] * 2 + smj[m]];
        Wd[f] = dup2f(wv * g_bnA1[c]);
    }
    for (int kk = t; kk < NV + 2; kk += 128) {
        int v = 0;
        if (kk < NV) {
            int c = kk & 15, m = kk >> 4;
            v = (c * 50 + (h2 + smi[m] - 1) * 5 + (w2 + smj[m] - 1)) * B_TOTAL;
        }
        soff[kk] = v;
    }
    if (t < 8) {
        float s = 0.f;
#pragma unroll
        for (int kk = 0; kk < NV; ++kk) {
            int c = kk & 15, m = kk >> 4;
            s += lcw[(size_t)((t * 16 + c) * 66 + loc) * 4 + smi[m] * 2 + smj[m]] * g_bnB1[c];
        }
        biasc[t] = s;
    }
    __syncthreads();

    const float* gA = g_y1 + B0 + t * 8;
    u64 acc[4][8] = {};
    ulonglong2 f0a, f0b, f1a, f1b;
    { const ulonglong2* p = (const ulonglong2*)(gA + soff[0]); f0a = p[0]; f0b = p[1]; }
    { const ulonglong2* p = (const ulonglong2*)(gA + soff[1]); f1a = p[0]; f1b = p[1]; }

#pragma unroll 4
    for (int k = 0; k < NV; k += 2) {
        LC_BODY(f0a, f0b, k);
        LC_BODY(f1a, f1b, k + 1);
    }

#pragma unroll
    for (int o = 0; o < 8; ++o) {
        const float bv = lcb[o * 66 + loc] + biasc[o];
        float v[8];
#pragma unroll
        for (int p = 0; p < 4; ++p) UNPK(v[2 * p], v[2 * p + 1], acc[p][o]);
#pragma unroll
        for (int p = 0; p < 8; ++p) v[p] = lrelu(v[p] + bv);
        float* dst = g_y2 + ((size_t)o * 66 + loc) * B_TOTAL + B0 + t * 8;
        ((float4*)dst)[0] = make_float4(v[0], v[1], v[2], v[3]);
        ((float4*)dst)[1] = make_float4(v[4], v[5], v[6], v[7]);
        float s = wsum(v[0]+v[1]+v[2]+v[3]+v[4]+v[5]+v[6]+v[7]);
        float q = wsum(v[0]*v[0]+v[1]*v[1]+v[2]*v[2]+v[3]*v[3]
                     + v[4]*v[4]+v[5]*v[5]+v[6]*v[6]+v[7]*v[7]);
        if ((t & 31) == 0) {
            atomicAdd(&red[o * 2 + 0], s);
            atomicAdd(&red[o * 2 + 1], q);
        }
    }
    __syncthreads();
    if (t < 16) g_part2[(by * 66 + loc) * 16 + t] = red[t];
}

__global__ void __launch_bounds__(128, 4) k3_lc2(const float* __restrict__ lcw,
                                                 const float* __restrict__ lcb) {
    __shared__ __align__(16) u64 Wd[512];
    __shared__ float biasc[8];
    __shared__ int soff[66];
    __shared__ float red[16];
    __shared__ int smi[4], smj[4];
    const int t   = threadIdx.x;
    const int loc = blockIdx.x;
    const int B0  = blockIdx.y * 1024;
    const int h2 = loc / 6, w2 = loc - h2 * 6;
    const int nI = (h2 == 0 || h2 == 10) ? 1 : 2;
    const int nJ = (w2 == 0 || w2 == 5) ? 1 : 2;
    const int nIJ = nI * nJ;
    if (nIJ == 4)      k3_body<4>(t, loc, h2, w2, B0, blockIdx.y, lcw, lcb, Wd, biasc, soff, red, smi, smj);
    else if (nIJ == 2) k3_body<2>(t, loc, h2, w2, B0, blockIdx.y, lcw, lcb, Wd, biasc, soff, red, smi, smj);
    else               k3_body<1>(t, loc, h2, w2, B0, blockIdx.y, lcw, lcb, Wd, biasc, soff, red, smi, smj);
}

// ============================ K5: BN2(folded) + LC3 ===========================
template<int NIJ>
__device__ __forceinline__ void k5_body(
    int t, int loc, int h3, int w3, int B0, int by,
    const float* __restrict__ lcw, const float* __restrict__ lcb,
    u64* Wd, float* biasc, int* soff, float* red, int* smi, int* smj) {
    constexpr int NV = NIJ * 8;

    const int ilo = (h3 == 0) ? 1 : 0;
    const int jlo = (w3 == 0) ? 1 : 0;
    const int nJ = (w3 == 0 || w3 == 3) ? 1 : 2;
    if (t < NIJ) { smi[t] = ilo + t / nJ; smj[t] = jlo + t - (t / nJ) * nJ; }
    if (t < 16) red[t] = 0.f;
    __syncthreads();

    {
        int f = t;
        if (f < NV * 8) {
            int kk = f >> 3, o = f & 7;
            int c = kk & 7, m = kk >> 3;
            float wv = lcw[(size_t)((o * 8 + c) * 48 + loc) * 4 + smi[m] * 2 + smj[m]];
            Wd[f] = dup2f(wv * g_bnA2[c]);
        }
        if (NV * 8 > 128) {
            f = 128 + t;
            if (f < NV * 8) {
                int kk = f >> 3, o = f & 7;
                int c = kk & 7, m = kk >> 3;
                float wv = lcw[(size_t)((o * 8 + c) * 48 + loc) * 4 + smi[m] * 2 + smj[m]];
                Wd[f] = dup2f(wv * g_bnA2[c]);
            }
        }
    }
    for (int kk = t; kk < NV + 2; kk += 128) {
        int v = 0;
        if (kk < NV) {
            int c = kk & 7, m = kk >> 3;
            v = (c * 66 + (h3 + smi[m] - 1) * 6 + (2 * w3 + smj[m] - 1)) * B_TOTAL;
        }
        soff[kk] = v;
    }
    if (t < 8) {
        float s = 0.f;
#pragma unroll
        for (int kk = 0; kk < NV; ++kk) {
            int c = kk & 7, m = kk >> 3;
            s += lcw[(size_t)((t * 8 + c) * 48 + loc) * 4 + smi[m] * 2 + smj[m]] * g_bnB2[c];
        }
        biasc[t] = s;
    }
    __syncthreads();

    const float* gA = g_y2 + B0 + t * 8;
    u64 acc[4][8] = {};
    ulonglong2 f0a, f0b, f1a, f1b;
    { const ulonglong2* p = (const ulonglong2*)(gA + soff[0]); f0a = p[0]; f0b = p[1]; }
    { const ulonglong2* p = (const ulonglong2*)(gA + soff[1]); f1a = p[0]; f1b = p[1]; }

#pragma unroll 4
    for (int k = 0; k < NV; k += 2) {
        LC_BODY(f0a, f0b, k);
        LC_BODY(f1a, f1b, k + 1);
    }

#pragma unroll
    for (int o = 0; o < 8; ++o) {
        const float bv = lcb[o * 48 + loc] + biasc[o];
        float v[8];
#pragma unroll
        for (int p = 0; p < 4; ++p) UNPK(v[2 * p], v[2 * p + 1], acc[p][o]);
#pragma unroll
        for (int p = 0; p < 8; ++p) v[p] = lrelu(v[p] + bv);
        float* dst = g_y3 + ((size_t)o * 48 + loc) * B_TOTAL + B0 + t * 8;
        ((float4*)dst)[0] = make_float4(v[0], v[1], v[2], v[3]);
        ((float4*)dst)[1] = make_float4(v[4], v[5], v[6], v[7]);
        float s = wsum(v[0]+v[1]+v[2]+v[3]+v[4]+v[5]+v[6]+v[7]);
        float q = wsum(v[0]*v[0]+v[1]*v[1]+v[2]*v[2]+v[3]*v[3]
                     + v[4]*v[4]+v[5]*v[5]+v[6]*v[6]+v[7]*v[7]);
        if ((t & 31) == 0) {
            atomicAdd(&red[o * 2 + 0], s);
            atomicAdd(&red[o * 2 + 1], q);
        }
    }
    __syncthreads();
    if (t < 16) g_part3[(by * 48 + loc) * 16 + t] = red[t];
}

__global__ void __launch_bounds__(128, 4) k5_lc3(const float* __restrict__ lcw,
                                                 const float* __restrict__ lcb) {
    __shared__ __align__(16) u64 Wd[256];
    __shared__ float biasc[8];
    __shared__ int soff[34];
    __shared__ float red[16];
    __shared__ int smi[4], smj[4];
    const int t   = threadIdx.x;
    const int loc = blockIdx.x;
    const int B0  = blockIdx.y * 1024;
    const int h3 = loc >> 2, w3 = loc & 3;
    const int nI = (h3 == 0 || h3 == 11) ? 1 : 2;
    const int nJ = (w3 == 0 || w3 == 3) ? 1 : 2;
    const int nIJ = nI * nJ;
    if (nIJ == 4)      k5_body<4>(t, loc, h3, w3, B0, blockIdx.y, lcw, lcb, Wd, biasc, soff, red, smi, smj);
    else if (nIJ == 2) k5_body<2>(t, loc, h3, w3, B0, blockIdx.y, lcw, lcb, Wd, biasc, soff, red, smi, smj);
    else               k5_body<1>(t, loc, h3, w3, B0, blockIdx.y, lcw, lcb, Wd, biasc, soff, red, smi, smj);
}

// ============================ stat reducer ====================================
__global__ void kred(int stage, int nb, int nch, float invN,
                     const float* __restrict__ gamma, const float* __restrict__ beta) {
    __shared__ float sm[1024];
    const float* part = (stage == 0) ? g_part1 : (stage == 1) ? g_part2 : g_part3;
    float* bnA = (stage == 0) ? g_bnA1 : (stage == 1) ? g_bnA2 : g_bnA3;
    float* bnB = (stage == 0) ? g_bnB1 : (stage == 1) ? g_bnB2 : g_bnB3;
    const int t = threadIdx.x;
    const int slots = 2 * nch;
    const int grp = t % slots;
    const int lane = t / slots;
    const int per = blockDim.x / slots;
    float s = 0.f;
    for (int i = lane; i < nb; i += per) s += part[i * slots + grp];
    sm[t] = s;
    __syncthreads();
    for (int step = per >> 1; step > 0; step >>= 1) {
        if (lane < step) sm[t] += sm[t + step * slots];
        __syncthreads();
    }
    if (t < nch) {
        float sum = sm[t * 2 + 0], sq = sm[t * 2 + 1];
        float mean = sum * invN;
        float var = sq * invN - mean * mean;
        float rs = rsqrtf(var + BN_EPS);
        float g = gamma[t];
        bnA[t] = g * rs;
        bnB[t] = beta[t] - mean * g * rs;
    }
}

// ============================ K7: BN3 + transpose to output ===================
__global__ void k7_out(float* __restrict__ out) {
    __shared__ float tile[32][65];
    __shared__ float a3[8], b3[8];
    const int t  = threadIdx.x;
    const int f0 = blockIdx.x * 32;
    const int b0 = blockIdx.y * 64;
    if (t < 8) { a3[t] = g_bnA3[t]; b3[t] = g_bnB3[t]; }
    __syncthreads();
#pragma unroll
    for (int r = 0; r < 8; ++r) {
        int f = r * 4 + (t >> 6);
        int b = t & 63;
        float v = g_y3[(size_t)(f0 + f) * B_TOTAL + b0 + b];
        int c = (f0 + f) / 48;
        tile[f][b] = fmaf(a3[c], v, b3[c]);
    }
    __syncthreads();
#pragma unroll
    for (int r = 0; r < 8; ++r) {
        int f = t & 31;
        int b = r * 8 + (t >> 5);
        out[(size_t)(b0 + b) * 384 + f0 + f] = tile[f][b];
    }
}

// ============================ launch ==========================================
extern "C" void kernel_launch(void* const* d_in, const int* in_sizes, int n_in,
                              void* d_out, int out_size) {
    const float* image = (const float*)d_in[0];
    const float* c1w   = (const float*)d_in[1];
    const float* c1b   = (const float*)d_in[2];
    const float* lc1w  = (const float*)d_in[3];
    const float* lc1b  = (const float*)d_in[4];
    const float* lc2w  = (const float*)d_in[5];
    const float* lc2b  = (const float*)d_in[6];
    const float* lc3w  = (const float*)d_in[7];
    const float* lc3b  = (const float*)d_in[8];
    const float* g1    = (const float*)d_in[9];
    const float* be1   = (const float*)d_in[10];
    const float* g2    = (const float*)d_in[11];
    const float* be2   = (const float*)d_in[12];
    const float* g3    = (const float*)d_in[13];
    const float* be3   = (const float*)d_in[14];
    float* out = (float*)d_out;

    cudaFuncSetAttribute(k0_conv1, cudaFuncAttributeMaxDynamicSharedMemorySize, SMEM0);

    k0_conv1<<<dim3(32, 8), 256, SMEM0>>>(image, c1w, c1b);
    k1_lc1  <<<dim3(50, 8), 256>>>(lc1w, lc1b);
    kred    <<<1, 1024>>>(0, 400, 16, 1.0f / (8192.0f * 50.0f), g1, be1);
    k3_lc2  <<<dim3(66, 8), 128>>>(lc2w, lc2b);
    kred    <<<1, 1024>>>(1, 528, 8, 1.0f / (8192.0f * 66.0f), g2, be2);
    k5_lc3  <<<dim3(48, 8), 128>>>(lc3w, lc3b);
    kred    <<<1, 1024>>>(2, 384, 8, 1.0f / (8192.0f * 48.0f), g3, be3);
    k7_out  <<<dim3(12, 128), 256>>>(out);
}